// round 10
// baseline (speedup 1.0000x reference)
#include <cuda_runtime.h>
#include <cuda_bf16.h>
#include <cstdint>
#include <math.h>

// ---------------- problem constants ----------------
#define T_TOKENS 8192
#define H_DIM    2048
#define I_DIM    1408
#define E_NUM    8
#define N1       (2*I_DIM)     // 2816
#define ENTRIES  (2*T_TOKENS)  // 16384 token-expert pairs

// ---------------- device scratch (static, no allocs) ----------------
__device__ __align__(16) __nv_bfloat16 g_xb  [(size_t)T_TOKENS * H_DIM];     // 33.6 MB
__device__ __align__(16) __nv_bfloat16 g_w13b[(size_t)E_NUM * N1 * H_DIM];   // 92.3 MB
__device__ __align__(16) __nv_bfloat16 g_w2b [(size_t)E_NUM * H_DIM * I_DIM];// 46.1 MB
__device__ __align__(16) __nv_bfloat16 g_ab  [(size_t)ENTRIES * I_DIM];      // 46.1 MB
__device__ __align__(16) float g_h[(size_t)ENTRIES * N1];                    // 184.5 MB
__device__ __align__(16) float g_y[(size_t)ENTRIES * H_DIM];                 // 134.2 MB
__device__ float g_xs[T_TOKENS];
__device__ float g_as[ENTRIES];
__device__ int   g_top_idx [T_TOKENS * 2];
__device__ float g_top_gate[T_TOKENS * 2];
__device__ int   g_counts[E_NUM];
__device__ int   g_bases [E_NUM];
__device__ int   g_cursor[E_NUM];
__device__ int   g_tok_list  [ENTRIES];
__device__ float g_entry_gate[ENTRIES];
__device__ int   g_entry_of  [ENTRIES];

// ---------------- helpers ----------------
__device__ __forceinline__ __nv_bfloat16 qb(float v, float s) {
    float r = rintf(v / s);                       // round-half-even == jnp.round
    r = fminf(fmaxf(r, -127.0f), 127.0f);
    return __float2bfloat16(r);                   // ints <=127 exact in bf16
}
__device__ __forceinline__ uint32_t smem_u32(const void* p) {
    uint32_t a;
    asm("{ .reg .u64 t; cvta.to.shared.u64 t, %1; cvt.u32.u64 %0, t; }" : "=r"(a) : "l"(p));
    return a;
}
__device__ __forceinline__ void ldm_x4(uint32_t* r, uint32_t addr) {
    asm volatile("ldmatrix.sync.aligned.m8n8.x4.shared.b16 {%0,%1,%2,%3}, [%4];"
        : "=r"(r[0]), "=r"(r[1]), "=r"(r[2]), "=r"(r[3]) : "r"(addr));
}
__device__ __forceinline__ void mma_bf16(float* d, const uint32_t* a, uint32_t b0, uint32_t b1) {
    asm volatile("mma.sync.aligned.m16n8k16.row.col.f32.bf16.bf16.f32 "
        "{%0,%1,%2,%3}, {%4,%5,%6,%7}, {%8,%9}, {%0,%1,%2,%3};"
        : "+f"(d[0]), "+f"(d[1]), "+f"(d[2]), "+f"(d[3])
        : "r"(a[0]), "r"(a[1]), "r"(a[2]), "r"(a[3]), "r"(b0), "r"(b1));
}
__device__ __forceinline__ void cp_async16(uint32_t dst, const void* src) {
    asm volatile("cp.async.cg.shared.global [%0], [%1], 16;"
                 :: "r"(dst), "l"(src) : "memory");
}

// ---------------- weight int32 -> bf16 ----------------
__global__ void __launch_bounds__(256) convb_kernel(const int* __restrict__ src,
                                                    int n8, int which) {
    int i = blockIdx.x * blockDim.x + threadIdx.x;
    if (i >= n8) return;
    const int4* s = reinterpret_cast<const int4*>(src) + 2 * (size_t)i;
    int4 a = s[0], b = s[1];
    __align__(16) __nv_bfloat16 o[8];
    o[0] = __float2bfloat16((float)a.x); o[1] = __float2bfloat16((float)a.y);
    o[2] = __float2bfloat16((float)a.z); o[3] = __float2bfloat16((float)a.w);
    o[4] = __float2bfloat16((float)b.x); o[5] = __float2bfloat16((float)b.y);
    o[6] = __float2bfloat16((float)b.z); o[7] = __float2bfloat16((float)b.w);
    __nv_bfloat16* dst = which ? g_w2b : g_w13b;
    *reinterpret_cast<uint4*>(dst + 8 * (size_t)i) = *reinterpret_cast<uint4*>(o);
}

// ---------------- init / prefix / scatter ----------------
__global__ void init_kernel() {
    if (threadIdx.x < E_NUM) g_counts[threadIdx.x] = 0;
}
__global__ void prefix_kernel() {
    if (threadIdx.x == 0 && blockIdx.x == 0) {
        int acc = 0;
        for (int e = 0; e < E_NUM; e++) { g_bases[e] = acc; g_cursor[e] = acc; acc += g_counts[e]; }
    }
}
__global__ void __launch_bounds__(256) scatter_kernel() {
    int t = blockIdx.x * blockDim.x + threadIdx.x;
    if (t >= T_TOKENS) return;
#pragma unroll
    for (int k = 0; k < 2; k++) {
        int e = g_top_idx[2 * t + k];
        int pos = atomicAdd(&g_cursor[e], 1);
        g_tok_list[pos]   = t;
        g_entry_gate[pos] = g_top_gate[2 * t + k];
        g_entry_of[2 * t + k] = pos;
    }
}

// ---------------- gating + dynamic int8 quant (stored as bf16) ----------------
__global__ void __launch_bounds__(256) gate_quant_kernel(const float* __restrict__ x,
                                                         const float* __restrict__ gw) {
    int t = blockIdx.x;
    int tid = threadIdx.x, lane = tid & 31, warp = tid >> 5;
    const float* xr = x + (size_t)t * H_DIM;

    float ps[E_NUM];
#pragma unroll
    for (int e = 0; e < E_NUM; e++) ps[e] = 0.0f;
    float pm = 0.0f;
    for (int j = tid; j < H_DIM; j += 256) {
        float v = xr[j];
        pm = fmaxf(pm, fabsf(v));
#pragma unroll
        for (int e = 0; e < E_NUM; e++) ps[e] = fmaf(v, gw[e * H_DIM + j], ps[e]);
    }
#pragma unroll
    for (int e = 0; e < E_NUM; e++)
        for (int off = 16; off; off >>= 1)
            ps[e] += __shfl_down_sync(0xffffffffu, ps[e], off);
    for (int off = 16; off; off >>= 1)
        pm = fmaxf(pm, __shfl_down_sync(0xffffffffu, pm, off));

    __shared__ float sl[8][E_NUM];
    __shared__ float sm[8];
    __shared__ float sS;
    if (lane == 0) {
#pragma unroll
        for (int e = 0; e < E_NUM; e++) sl[warp][e] = ps[e];
        sm[warp] = pm;
    }
    __syncthreads();
    if (tid == 0) {
        float logit[E_NUM]; float mx = 0.0f;
#pragma unroll
        for (int e = 0; e < E_NUM; e++) {
            float l = 0.0f;
            for (int w = 0; w < 8; w++) l += sl[w][e];
            logit[e] = l;
        }
        for (int w = 0; w < 8; w++) mx = fmaxf(mx, sm[w]);
        float s = fmaxf(mx / 127.0f, 1e-8f);
        g_xs[t] = s; sS = s;
        int e0 = 0;
        for (int e = 1; e < E_NUM; e++) if (logit[e] > logit[e0]) e0 = e;
        int e1 = -1;
        for (int e = 0; e < E_NUM; e++)
            if (e != e0 && (e1 < 0 || logit[e] > logit[e1])) e1 = e;
        float g0 = 1.0f / (1.0f + expf(logit[e1] - logit[e0]));
        g_top_idx [2 * t]     = e0;
        g_top_idx [2 * t + 1] = e1;
        g_top_gate[2 * t]     = g0;
        g_top_gate[2 * t + 1] = 1.0f - g0;
        atomicAdd(&g_counts[e0], 1);
        atomicAdd(&g_counts[e1], 1);
    }
    __syncthreads();
    float s = sS;
    const float4* x4 = reinterpret_cast<const float4*>(xr);
    int w = tid;   // 2048/8 == 256 groups, exactly one per thread
    float4 v0 = x4[2 * w], v1 = x4[2 * w + 1];
    __align__(16) __nv_bfloat16 q[8] = {
        qb(v0.x, s), qb(v0.y, s), qb(v0.z, s), qb(v0.w, s),
        qb(v1.x, s), qb(v1.y, s), qb(v1.z, s), qb(v1.w, s)};
    *reinterpret_cast<uint4*>(g_xb + (size_t)t * H_DIM + 8 * w) = *reinterpret_cast<uint4*>(q);
}

// ---------------- HMMA grouped GEMM (bf16 operands, fp32 accum) ----------------
// CTA tile 128x256, K-chunk 64 bf16 (128B rows), 8 warps (2x4), warp tile 64x64.
// SMEM: 3-stage pipeline, per stage 16KB A + 32KB B, chunk-xor swizzle.
template <int NKT, bool FC1>   // NKT = K/64
__global__ void __launch_bounds__(256) gemm_kernel(const float* __restrict__ wscale) {
    const int e   = blockIdx.z;
    const int cnt = g_counts[e];
    const int m0  = blockIdx.y * 128;
    if (m0 >= cnt) return;
    const int n0  = blockIdx.x * 256;
    const int base = g_bases[e];
    const int NTOT = FC1 ? N1 : H_DIM;

    extern __shared__ char smem_raw[];
    char* smem = (char*)(((uintptr_t)smem_raw + 1023) & ~(uintptr_t)1023);
    const uint32_t sbase = smem_u32(smem);
    // stage s: A at s*49152, B at s*49152 + 16384

    const int tid  = threadIdx.x;
    const int wid  = tid >> 5;
    const int lane = tid & 31;

    // ---- cp.async mapping ----
    // A: 128 rows x 8 chunks(16B): thread t -> row t>>1, chunks (t&1)*4+0..3
    // B: 256 rows x 8 chunks:      thread t -> row t,    chunks 0..7
    const int arow = tid >> 1;
    const int ac0  = (tid & 1) * 4;
    int am = m0 + arow; if (am > cnt - 1) am = cnt - 1;
    const char* a_src;
    const char* b_src;
    if (FC1) {
        a_src = (const char*)(g_xb + (size_t)g_tok_list[base + am] * H_DIM);
        b_src = (const char*)(g_w13b + ((size_t)e * N1 + n0 + tid) * H_DIM);
    } else {
        a_src = (const char*)(g_ab + (size_t)(base + am) * I_DIM);
        b_src = (const char*)(g_w2b + ((size_t)e * H_DIM + n0 + tid) * I_DIM);
    }
    uint32_t adst[4];
#pragma unroll
    for (int j = 0; j < 4; j++)
        adst[j] = (uint32_t)(arow * 128 + 16 * ((ac0 + j) ^ (arow & 7)));
    uint32_t bdst[8];
#pragma unroll
    for (int j = 0; j < 8; j++)
        bdst[j] = (uint32_t)(tid * 128 + 16 * (j ^ (tid & 7)));

    auto issue = [&](int kt, int buf) {
        uint32_t abuf = sbase + (uint32_t)buf * 49152u;
        uint32_t bbuf = abuf + 16384u;
        const char* as = a_src + kt * 128;   // 64 bf16 = 128 bytes per chunk
        const char* bs = b_src + kt * 128;
#pragma unroll
        for (int j = 0; j < 4; j++)
            cp_async16(abuf + adst[j], as + (ac0 + j) * 16);
#pragma unroll
        for (int j = 0; j < 8; j++)
            cp_async16(bbuf + bdst[j], bs + j * 16);
        asm volatile("cp.async.commit_group;" ::: "memory");
    };

    // ---- fragment addressing (canonical ldmatrix.x4 patterns) ----
    const int wm = (wid >> 2) * 64;   // warp M offset: 0 or 64
    const int wn = (wid & 3) * 64;    // warp N offset: 0,64,128,192

    uint32_t a_off[4]; int a_s[4];
    const int a_hi = lane >> 4;                // 16B half of k16 step
#pragma unroll
    for (int ma = 0; ma < 4; ma++) {
        int r = wm + ma * 16 + (lane & 15);
        a_off[ma] = (uint32_t)(r * 128);
        a_s[ma]   = r & 7;
    }
    uint32_t b_off[4]; int b_s[4];
    const int b_hi = (lane >> 3) & 1;
#pragma unroll
    for (int p = 0; p < 4; p++) {
        int r = wn + p * 16 + (lane & 7) + ((lane >> 4) << 3);
        b_off[p] = (uint32_t)(r * 128);
        b_s[p]   = r & 7;
    }

    float acc[4][8][4];
#pragma unroll
    for (int i = 0; i < 4; i++)
#pragma unroll
        for (int j = 0; j < 8; j++)
#pragma unroll
            for (int k = 0; k < 4; k++) acc[i][j][k] = 0.0f;

    issue(0, 0);
    if (NKT > 1) issue(1, 1);
    if (NKT > 2) issue(2, 2);

    int buf = 0;
    for (int kt = 0; kt < NKT; kt++) {
        if (kt + 2 < NKT)
            asm volatile("cp.async.wait_group 2;" ::: "memory");
        else if (kt + 1 < NKT)
            asm volatile("cp.async.wait_group 1;" ::: "memory");
        else
            asm volatile("cp.async.wait_group 0;" ::: "memory");
        __syncthreads();

        uint32_t abuf = sbase + (uint32_t)buf * 49152u;
        uint32_t bbuf = abuf + 16384u;
#pragma unroll
        for (int ks = 0; ks < 4; ks++) {       // 4 x k16 per 64-elem chunk
            uint32_t af[4][4];
#pragma unroll
            for (int ma = 0; ma < 4; ma++)
                ldm_x4(af[ma], abuf + a_off[ma] + 16u * (uint32_t)((2 * ks + a_hi) ^ a_s[ma]));
            uint32_t bf[4][4];
#pragma unroll
            for (int p = 0; p < 4; p++)
                ldm_x4(bf[p], bbuf + b_off[p] + 16u * (uint32_t)((2 * ks + b_hi) ^ b_s[p]));
#pragma unroll
            for (int ma = 0; ma < 4; ma++) {
#pragma unroll
                for (int na = 0; na < 8; na++) {
                    int p = na >> 1, q = (na & 1) * 2;
                    mma_bf16(acc[ma][na], af[ma], bf[p][q], bf[p][q + 1]);
                }
            }
        }
        __syncthreads();
        if (kt + 3 < NKT) issue(kt + 3, buf);
        buf = (buf == 2) ? 0 : buf + 1;
    }

    // ---- epilogue: scale and store ----
    const int qn = (lane & 3) * 2;
    float2 wsc[8];
#pragma unroll
    for (int na = 0; na < 8; na++)
        wsc[na] = *reinterpret_cast<const float2*>(&wscale[e * NTOT + n0 + wn + na * 8 + qn]);

#pragma unroll
    for (int ma = 0; ma < 4; ma++) {
#pragma unroll
        for (int h = 0; h < 2; h++) {
            int m = m0 + wm + ma * 16 + (lane >> 2) + h * 8;
            if (m >= cnt) continue;
            int entry = base + m;
            float fsc;
            float* orow;
            if (FC1) { fsc = g_xs[g_tok_list[entry]]; orow = g_h + (size_t)entry * N1; }
            else     { fsc = g_as[entry] * g_entry_gate[entry]; orow = g_y + (size_t)entry * H_DIM; }
#pragma unroll
            for (int na = 0; na < 8; na++) {
                float2 o;
                o.x = acc[ma][na][2 * h + 0] * fsc * wsc[na].x;
                o.y = acc[ma][na][2 * h + 1] * fsc * wsc[na].y;
                *reinterpret_cast<float2*>(orow + n0 + wn + na * 8 + qn) = o;
            }
        }
    }
}

// ---------------- SwiGLU + dynamic int8 re-quant (stored as bf16) ----------------
__global__ void __launch_bounds__(256) swiglu_quant_kernel() {
    int entry = blockIdx.x;
    int tid = threadIdx.x, lane = tid & 31, warp = tid >> 5;
    const float* hr = g_h + (size_t)entry * N1;

    __shared__ __align__(16) float a_sh[I_DIM];
    __shared__ float wmax[8];
    __shared__ float sS;

    float pm = 0.0f;
    for (int i = tid; i < I_DIM; i += 256) {
        float h1 = hr[i];
        float h2 = hr[i + I_DIM];
        float a = h1 / (1.0f + expf(-h1)) * h2;
        a_sh[i] = a;
        pm = fmaxf(pm, fabsf(a));
    }
    for (int off = 16; off; off >>= 1)
        pm = fmaxf(pm, __shfl_down_sync(0xffffffffu, pm, off));
    if (lane == 0) wmax[warp] = pm;
    __syncthreads();
    if (tid == 0) {
        float mx = 0.0f;
        for (int w = 0; w < 8; w++) mx = fmaxf(mx, wmax[w]);
        float s = fmaxf(mx / 127.0f, 1e-8f);
        g_as[entry] = s; sS = s;
    }
    __syncthreads();
    float s = sS;
    if (tid < I_DIM / 8) {   // 176 groups of 8
        float4 v0 = *reinterpret_cast<const float4*>(&a_sh[8 * tid]);
        float4 v1 = *reinterpret_cast<const float4*>(&a_sh[8 * tid + 4]);
        __align__(16) __nv_bfloat16 q[8] = {
            qb(v0.x, s), qb(v0.y, s), qb(v0.z, s), qb(v0.w, s),
            qb(v1.x, s), qb(v1.y, s), qb(v1.z, s), qb(v1.w, s)};
        *reinterpret_cast<uint4*>(g_ab + (size_t)entry * I_DIM + 8 * tid) =
            *reinterpret_cast<uint4*>(q);
    }
}

// ---------------- combine ----------------
__global__ void __launch_bounds__(256) combine_kernel(const float* __restrict__ shared_out,
                                                      float* __restrict__ out) {
    int t = blockIdx.x;
    int p0 = g_entry_of[2 * t];
    int p1 = g_entry_of[2 * t + 1];
    const float4* s4 = reinterpret_cast<const float4*>(shared_out + (size_t)t * H_DIM);
    const float4* y0 = reinterpret_cast<const float4*>(g_y + (size_t)p0 * H_DIM);
    const float4* y1 = reinterpret_cast<const float4*>(g_y + (size_t)p1 * H_DIM);
    float4* o4 = reinterpret_cast<float4*>(out + (size_t)t * H_DIM);
    for (int w = threadIdx.x; w < H_DIM / 4; w += 256) {
        float4 a = s4[w], b = y0[w], c = y1[w];
        float4 r;
        r.x = a.x + b.x + c.x; r.y = a.y + b.y + c.y;
        r.z = a.z + b.z + c.z; r.w = a.w + b.w + c.w;
        o4[w] = r;
    }
}

// ---------------- launch ----------------
extern "C" void kernel_launch(void* const* d_in, const int* in_sizes, int n_in,
                              void* d_out, int out_size) {
    const float* x    = (const float*)d_in[0];
    const float* gw   = (const float*)d_in[1];
    const int*   w13q = (const int*)  d_in[2];
    const float* w13s = (const float*)d_in[3];
    const int*   w2q  = (const int*)  d_in[4];
    const float* w2s  = (const float*)d_in[5];
    const float* shr  = (const float*)d_in[6];
    float* out = (float*)d_out;

    const int SMEM_SZ = 1024 + 3 * 49152;   // align slack + 3-stage A/B
    static bool attr_set = false;
    if (!attr_set) {
        cudaFuncSetAttribute(gemm_kernel<32, true>,
                             cudaFuncAttributeMaxDynamicSharedMemorySize, SMEM_SZ);
        cudaFuncSetAttribute(gemm_kernel<22, false>,
                             cudaFuncAttributeMaxDynamicSharedMemorySize, SMEM_SZ);
        attr_set = true;
    }

    const int n8_w13 = E_NUM * N1 * H_DIM / 8;     // 5,767,168
    const int n8_w2  = E_NUM * H_DIM * I_DIM / 8;  // 2,883,584

    convb_kernel<<<(n8_w13 + 255) / 256, 256>>>(w13q, n8_w13, 0);
    convb_kernel<<<(n8_w2  + 255) / 256, 256>>>(w2q,  n8_w2,  1);
    init_kernel<<<1, 32>>>();
    gate_quant_kernel<<<T_TOKENS, 256>>>(x, gw);
    prefix_kernel<<<1, 32>>>();
    scatter_kernel<<<(T_TOKENS + 255) / 256, 256>>>();
    gemm_kernel<32, true><<<dim3(N1 / 256, T_TOKENS / 128, E_NUM), 256, SMEM_SZ>>>(w13s);
    swiglu_quant_kernel<<<ENTRIES, 256>>>();
    gemm_kernel<22, false><<<dim3(H_DIM / 256, T_TOKENS / 128, E_NUM), 256, SMEM_SZ>>>(w2s);
    combine_kernel<<<T_TOKENS, 256>>>(shr, out);
}

// round 11
// speedup vs baseline: 1.2408x; 1.2408x over previous
#include <cuda_runtime.h>
#include <cuda_bf16.h>
#include <cstdint>
#include <math.h>

// ---------------- problem constants ----------------
#define T_TOKENS 8192
#define H_DIM    2048
#define I_DIM    1408
#define E_NUM    8
#define N1       (2*I_DIM)     // 2816
#define ENTRIES  (2*T_TOKENS)  // 16384 token-expert pairs

// ---------------- device scratch (static, no allocs) ----------------
__device__ __align__(16) __nv_bfloat16 g_xb  [(size_t)T_TOKENS * H_DIM];     // 33.6 MB
__device__ __align__(16) __nv_bfloat16 g_w13b[(size_t)E_NUM * N1 * H_DIM];   // 92.3 MB
__device__ __align__(16) __nv_bfloat16 g_w2b [(size_t)E_NUM * H_DIM * I_DIM];// 46.1 MB
__device__ __align__(16) __nv_bfloat16 g_ab  [(size_t)ENTRIES * I_DIM];      // 46.1 MB
__device__ __align__(16) float g_h[(size_t)ENTRIES * N1];                    // 184.5 MB
__device__ __align__(16) float g_y[(size_t)ENTRIES * H_DIM];                 // 134.2 MB
__device__ float g_xs[T_TOKENS];
__device__ float g_as[ENTRIES];
__device__ int   g_top_idx [T_TOKENS * 2];
__device__ float g_top_gate[T_TOKENS * 2];
__device__ int   g_counts[E_NUM];
__device__ int   g_bases [E_NUM];
__device__ int   g_cursor[E_NUM];
__device__ int   g_tok_list  [ENTRIES];
__device__ float g_entry_gate[ENTRIES];
__device__ int   g_entry_of  [ENTRIES];

// ---------------- helpers ----------------
__device__ __forceinline__ __nv_bfloat16 qb(float v, float s) {
    float r = rintf(v / s);                       // round-half-even == jnp.round
    r = fminf(fmaxf(r, -127.0f), 127.0f);
    return __float2bfloat16(r);                   // ints <=127 exact in bf16
}
__device__ __forceinline__ uint32_t smem_u32(const void* p) {
    uint32_t a;
    asm("{ .reg .u64 t; cvta.to.shared.u64 t, %1; cvt.u32.u64 %0, t; }" : "=r"(a) : "l"(p));
    return a;
}
__device__ __forceinline__ void ldm_x4(uint32_t* r, uint32_t addr) {
    asm volatile("ldmatrix.sync.aligned.m8n8.x4.shared.b16 {%0,%1,%2,%3}, [%4];"
        : "=r"(r[0]), "=r"(r[1]), "=r"(r[2]), "=r"(r[3]) : "r"(addr));
}
__device__ __forceinline__ void mma_bf16(float* d, const uint32_t* a, uint32_t b0, uint32_t b1) {
    asm volatile("mma.sync.aligned.m16n8k16.row.col.f32.bf16.bf16.f32 "
        "{%0,%1,%2,%3}, {%4,%5,%6,%7}, {%8,%9}, {%0,%1,%2,%3};"
        : "+f"(d[0]), "+f"(d[1]), "+f"(d[2]), "+f"(d[3])
        : "r"(a[0]), "r"(a[1]), "r"(a[2]), "r"(a[3]), "r"(b0), "r"(b1));
}
__device__ __forceinline__ void cp_async16(uint32_t dst, const void* src) {
    asm volatile("cp.async.cg.shared.global [%0], [%1], 16;"
                 :: "r"(dst), "l"(src) : "memory");
}

// ---------------- weight int32 -> bf16 ----------------
__global__ void __launch_bounds__(256) convb_kernel(const int* __restrict__ src,
                                                    int n8, int which) {
    int i = blockIdx.x * blockDim.x + threadIdx.x;
    if (i >= n8) return;
    const int4* s = reinterpret_cast<const int4*>(src) + 2 * (size_t)i;
    int4 a = s[0], b = s[1];
    __align__(16) __nv_bfloat16 o[8];
    o[0] = __float2bfloat16((float)a.x); o[1] = __float2bfloat16((float)a.y);
    o[2] = __float2bfloat16((float)a.z); o[3] = __float2bfloat16((float)a.w);
    o[4] = __float2bfloat16((float)b.x); o[5] = __float2bfloat16((float)b.y);
    o[6] = __float2bfloat16((float)b.z); o[7] = __float2bfloat16((float)b.w);
    __nv_bfloat16* dst = which ? g_w2b : g_w13b;
    *reinterpret_cast<uint4*>(dst + 8 * (size_t)i) = *reinterpret_cast<uint4*>(o);
}

// ---------------- init / prefix / scatter ----------------
__global__ void init_kernel() {
    if (threadIdx.x < E_NUM) g_counts[threadIdx.x] = 0;
}
__global__ void prefix_kernel() {
    if (threadIdx.x == 0 && blockIdx.x == 0) {
        int acc = 0;
        for (int e = 0; e < E_NUM; e++) { g_bases[e] = acc; g_cursor[e] = acc; acc += g_counts[e]; }
    }
}
__global__ void __launch_bounds__(256) scatter_kernel() {
    int t = blockIdx.x * blockDim.x + threadIdx.x;
    if (t >= T_TOKENS) return;
#pragma unroll
    for (int k = 0; k < 2; k++) {
        int e = g_top_idx[2 * t + k];
        int pos = atomicAdd(&g_cursor[e], 1);
        g_tok_list[pos]   = t;
        g_entry_gate[pos] = g_top_gate[2 * t + k];
        g_entry_of[2 * t + k] = pos;
    }
}

// ---------------- gating + dynamic int8 quant (stored as bf16) ----------------
__global__ void __launch_bounds__(256) gate_quant_kernel(const float* __restrict__ x,
                                                         const float* __restrict__ gw) {
    int t = blockIdx.x;
    int tid = threadIdx.x, lane = tid & 31, warp = tid >> 5;
    const float* xr = x + (size_t)t * H_DIM;

    float ps[E_NUM];
#pragma unroll
    for (int e = 0; e < E_NUM; e++) ps[e] = 0.0f;
    float pm = 0.0f;
    for (int j = tid; j < H_DIM; j += 256) {
        float v = xr[j];
        pm = fmaxf(pm, fabsf(v));
#pragma unroll
        for (int e = 0; e < E_NUM; e++) ps[e] = fmaf(v, gw[e * H_DIM + j], ps[e]);
    }
#pragma unroll
    for (int e = 0; e < E_NUM; e++)
        for (int off = 16; off; off >>= 1)
            ps[e] += __shfl_down_sync(0xffffffffu, ps[e], off);
    for (int off = 16; off; off >>= 1)
        pm = fmaxf(pm, __shfl_down_sync(0xffffffffu, pm, off));

    __shared__ float sl[8][E_NUM];
    __shared__ float sm[8];
    __shared__ float sS;
    if (lane == 0) {
#pragma unroll
        for (int e = 0; e < E_NUM; e++) sl[warp][e] = ps[e];
        sm[warp] = pm;
    }
    __syncthreads();
    if (tid == 0) {
        float logit[E_NUM]; float mx = 0.0f;
#pragma unroll
        for (int e = 0; e < E_NUM; e++) {
            float l = 0.0f;
            for (int w = 0; w < 8; w++) l += sl[w][e];
            logit[e] = l;
        }
        for (int w = 0; w < 8; w++) mx = fmaxf(mx, sm[w]);
        float s = fmaxf(mx / 127.0f, 1e-8f);
        g_xs[t] = s; sS = s;
        int e0 = 0;
        for (int e = 1; e < E_NUM; e++) if (logit[e] > logit[e0]) e0 = e;
        int e1 = -1;
        for (int e = 0; e < E_NUM; e++)
            if (e != e0 && (e1 < 0 || logit[e] > logit[e1])) e1 = e;
        float g0 = 1.0f / (1.0f + expf(logit[e1] - logit[e0]));
        g_top_idx [2 * t]     = e0;
        g_top_idx [2 * t + 1] = e1;
        g_top_gate[2 * t]     = g0;
        g_top_gate[2 * t + 1] = 1.0f - g0;
        atomicAdd(&g_counts[e0], 1);
        atomicAdd(&g_counts[e1], 1);
    }
    __syncthreads();
    float s = sS;
    const float4* x4 = reinterpret_cast<const float4*>(xr);
    int w = tid;   // 2048/8 == 256 groups, exactly one per thread
    float4 v0 = x4[2 * w], v1 = x4[2 * w + 1];
    __align__(16) __nv_bfloat16 q[8] = {
        qb(v0.x, s), qb(v0.y, s), qb(v0.z, s), qb(v0.w, s),
        qb(v1.x, s), qb(v1.y, s), qb(v1.z, s), qb(v1.w, s)};
    *reinterpret_cast<uint4*>(g_xb + (size_t)t * H_DIM + 8 * w) = *reinterpret_cast<uint4*>(q);
}

// ---------------- HMMA grouped GEMM (bf16 operands, fp32 accum) ----------------
// CTA tile 128x128, K-chunk 64 bf16 (128B rows), 8 warps (2x4), warp tile 64x32.
// SMEM: 3-stage pipeline (16KB A + 16KB B per stage), chunk-xor swizzle.
template <int NKT, bool FC1>   // NKT = K/64
__global__ void __launch_bounds__(256, 2) gemm_kernel(const float* __restrict__ wscale) {
    const int e   = blockIdx.z;
    const int cnt = g_counts[e];
    const int m0  = blockIdx.y * 128;
    if (m0 >= cnt) return;
    const int n0  = blockIdx.x * 128;
    const int base = g_bases[e];
    const int NTOT = FC1 ? N1 : H_DIM;

    extern __shared__ char smem_raw[];
    char* smem = (char*)(((uintptr_t)smem_raw + 1023) & ~(uintptr_t)1023);
    const uint32_t sbase = smem_u32(smem);
    // stage s: A at s*32768, B at s*32768 + 16384

    const int tid  = threadIdx.x;
    const int wid  = tid >> 5;
    const int lane = tid & 31;

    // ---- cp.async mapping: thread t -> row t>>1, 16B chunks (t&1)*4 + 0..3 ----
    const int lrow = tid >> 1;
    const int lc0  = (tid & 1) * 4;
    int am = m0 + lrow; if (am > cnt - 1) am = cnt - 1;
    const char* a_src;
    const char* b_src;
    if (FC1) {
        a_src = (const char*)(g_xb + (size_t)g_tok_list[base + am] * H_DIM);
        b_src = (const char*)(g_w13b + ((size_t)e * N1 + n0 + lrow) * H_DIM);
    } else {
        a_src = (const char*)(g_ab + (size_t)(base + am) * I_DIM);
        b_src = (const char*)(g_w2b + ((size_t)e * H_DIM + n0 + lrow) * I_DIM);
    }
    uint32_t dsto[4];
#pragma unroll
    for (int j = 0; j < 4; j++)
        dsto[j] = (uint32_t)(lrow * 128 + 16 * ((lc0 + j) ^ (lrow & 7)));

    auto issue = [&](int kt, int buf) {
        uint32_t abuf = sbase + (uint32_t)buf * 32768u;
        uint32_t bbuf = abuf + 16384u;
        const char* as = a_src + kt * 128;   // 64 bf16 = 128 bytes per chunk
        const char* bs = b_src + kt * 128;
#pragma unroll
        for (int j = 0; j < 4; j++) {
            cp_async16(abuf + dsto[j], as + (lc0 + j) * 16);
            cp_async16(bbuf + dsto[j], bs + (lc0 + j) * 16);
        }
        asm volatile("cp.async.commit_group;" ::: "memory");
    };

    // ---- fragment addressing (canonical ldmatrix.x4 patterns) ----
    const int wm = (wid >> 2) * 64;   // warp M offset: 0 or 64
    const int wn = (wid & 3) * 32;    // warp N offset: 0,32,64,96

    uint32_t a_off[4]; int a_s[4];
    const int a_hi = lane >> 4;                // 16B half of k16 step
#pragma unroll
    for (int ma = 0; ma < 4; ma++) {
        int r = wm + ma * 16 + (lane & 15);
        a_off[ma] = (uint32_t)(r * 128);
        a_s[ma]   = r & 7;
    }
    uint32_t b_off[2]; int b_s[2];
    const int b_hi = (lane >> 3) & 1;
#pragma unroll
    for (int p = 0; p < 2; p++) {
        int r = wn + p * 16 + (lane & 7) + ((lane >> 4) << 3);
        b_off[p] = (uint32_t)(r * 128);
        b_s[p]   = r & 7;
    }

    float acc[4][4][4];
#pragma unroll
    for (int i = 0; i < 4; i++)
#pragma unroll
        for (int j = 0; j < 4; j++)
#pragma unroll
            for (int k = 0; k < 4; k++) acc[i][j][k] = 0.0f;

    issue(0, 0);
    if (NKT > 1) issue(1, 1);
    if (NKT > 2) issue(2, 2);

    int buf = 0;
    for (int kt = 0; kt < NKT; kt++) {
        if (kt + 3 <= NKT - 1)
            asm volatile("cp.async.wait_group 2;" ::: "memory");
        else if (kt + 2 <= NKT - 1)
            asm volatile("cp.async.wait_group 1;" ::: "memory");
        else
            asm volatile("cp.async.wait_group 0;" ::: "memory");
        __syncthreads();

        uint32_t abuf = sbase + (uint32_t)buf * 32768u;
        uint32_t bbuf = abuf + 16384u;
#pragma unroll
        for (int ks = 0; ks < 4; ks++) {       // 4 x k16 per 64-elem chunk
            uint32_t af[4][4];
#pragma unroll
            for (int ma = 0; ma < 4; ma++)
                ldm_x4(af[ma], abuf + a_off[ma] + 16u * (uint32_t)((2 * ks + a_hi) ^ a_s[ma]));
            uint32_t bf[2][4];
#pragma unroll
            for (int p = 0; p < 2; p++)
                ldm_x4(bf[p], bbuf + b_off[p] + 16u * (uint32_t)((2 * ks + b_hi) ^ b_s[p]));
#pragma unroll
            for (int ma = 0; ma < 4; ma++) {
#pragma unroll
                for (int na = 0; na < 4; na++) {
                    int p = na >> 1, q = (na & 1) * 2;
                    mma_bf16(acc[ma][na], af[ma], bf[p][q], bf[p][q + 1]);
                }
            }
        }
        __syncthreads();
        if (kt + 3 < NKT) issue(kt + 3, buf);
        buf = (buf == 2) ? 0 : buf + 1;
    }

    // ---- epilogue: scale and store ----
    const int qn = (lane & 3) * 2;
    float2 wsc[4];
#pragma unroll
    for (int na = 0; na < 4; na++)
        wsc[na] = *reinterpret_cast<const float2*>(&wscale[e * NTOT + n0 + wn + na * 8 + qn]);

#pragma unroll
    for (int ma = 0; ma < 4; ma++) {
#pragma unroll
        for (int h = 0; h < 2; h++) {
            int m = m0 + wm + ma * 16 + (lane >> 2) + h * 8;
            if (m >= cnt) continue;
            int entry = base + m;
            float fsc;
            float* orow;
            if (FC1) { fsc = g_xs[g_tok_list[entry]]; orow = g_h + (size_t)entry * N1; }
            else     { fsc = g_as[entry] * g_entry_gate[entry]; orow = g_y + (size_t)entry * H_DIM; }
#pragma unroll
            for (int na = 0; na < 4; na++) {
                float2 o;
                o.x = acc[ma][na][2 * h + 0] * fsc * wsc[na].x;
                o.y = acc[ma][na][2 * h + 1] * fsc * wsc[na].y;
                *reinterpret_cast<float2*>(orow + n0 + wn + na * 8 + qn) = o;
            }
        }
    }
}

// ---------------- SwiGLU + dynamic int8 re-quant (stored as bf16) ----------------
__global__ void __launch_bounds__(256) swiglu_quant_kernel() {
    int entry = blockIdx.x;
    int tid = threadIdx.x, lane = tid & 31, warp = tid >> 5;
    const float* hr = g_h + (size_t)entry * N1;

    __shared__ __align__(16) float a_sh[I_DIM];
    __shared__ float wmax[8];
    __shared__ float sS;

    float pm = 0.0f;
    for (int i = tid; i < I_DIM; i += 256) {
        float h1 = hr[i];
        float h2 = hr[i + I_DIM];
        float a = h1 / (1.0f + expf(-h1)) * h2;
        a_sh[i] = a;
        pm = fmaxf(pm, fabsf(a));
    }
    for (int off = 16; off; off >>= 1)
        pm = fmaxf(pm, __shfl_down_sync(0xffffffffu, pm, off));
    if (lane == 0) wmax[warp] = pm;
    __syncthreads();
    if (tid == 0) {
        float mx = 0.0f;
        for (int w = 0; w < 8; w++) mx = fmaxf(mx, wmax[w]);
        float s = fmaxf(mx / 127.0f, 1e-8f);
        g_as[entry] = s; sS = s;
    }
    __syncthreads();
    float s = sS;
    if (tid < I_DIM / 8) {   // 176 groups of 8
        float4 v0 = *reinterpret_cast<const float4*>(&a_sh[8 * tid]);
        float4 v1 = *reinterpret_cast<const float4*>(&a_sh[8 * tid + 4]);
        __align__(16) __nv_bfloat16 q[8] = {
            qb(v0.x, s), qb(v0.y, s), qb(v0.z, s), qb(v0.w, s),
            qb(v1.x, s), qb(v1.y, s), qb(v1.z, s), qb(v1.w, s)};
        *reinterpret_cast<uint4*>(g_ab + (size_t)entry * I_DIM + 8 * tid) =
            *reinterpret_cast<uint4*>(q);
    }
}

// ---------------- combine ----------------
__global__ void __launch_bounds__(256) combine_kernel(const float* __restrict__ shared_out,
                                                      float* __restrict__ out) {
    int t = blockIdx.x;
    int p0 = g_entry_of[2 * t];
    int p1 = g_entry_of[2 * t + 1];
    const float4* s4 = reinterpret_cast<const float4*>(shared_out + (size_t)t * H_DIM);
    const float4* y0 = reinterpret_cast<const float4*>(g_y + (size_t)p0 * H_DIM);
    const float4* y1 = reinterpret_cast<const float4*>(g_y + (size_t)p1 * H_DIM);
    float4* o4 = reinterpret_cast<float4*>(out + (size_t)t * H_DIM);
    for (int w = threadIdx.x; w < H_DIM / 4; w += 256) {
        float4 a = s4[w], b = y0[w], c = y1[w];
        float4 r;
        r.x = a.x + b.x + c.x; r.y = a.y + b.y + c.y;
        r.z = a.z + b.z + c.z; r.w = a.w + b.w + c.w;
        o4[w] = r;
    }
}

// ---------------- launch ----------------
extern "C" void kernel_launch(void* const* d_in, const int* in_sizes, int n_in,
                              void* d_out, int out_size) {
    const float* x    = (const float*)d_in[0];
    const float* gw   = (const float*)d_in[1];
    const int*   w13q = (const int*)  d_in[2];
    const float* w13s = (const float*)d_in[3];
    const int*   w2q  = (const int*)  d_in[4];
    const float* w2s  = (const float*)d_in[5];
    const float* shr  = (const float*)d_in[6];
    float* out = (float*)d_out;

    const int SMEM_SZ = 1024 + 3 * 32768;   // align slack + 3-stage A/B
    static bool attr_set = false;
    if (!attr_set) {
        cudaFuncSetAttribute(gemm_kernel<32, true>,
                             cudaFuncAttributeMaxDynamicSharedMemorySize, SMEM_SZ);
        cudaFuncSetAttribute(gemm_kernel<22, false>,
                             cudaFuncAttributeMaxDynamicSharedMemorySize, SMEM_SZ);
        attr_set = true;
    }

    const int n8_w13 = E_NUM * N1 * H_DIM / 8;     // 5,767,168
    const int n8_w2  = E_NUM * H_DIM * I_DIM / 8;  // 2,883,584

    convb_kernel<<<(n8_w13 + 255) / 256, 256>>>(w13q, n8_w13, 0);
    convb_kernel<<<(n8_w2  + 255) / 256, 256>>>(w2q,  n8_w2,  1);
    init_kernel<<<1, 32>>>();
    gate_quant_kernel<<<T_TOKENS, 256>>>(x, gw);
    prefix_kernel<<<1, 32>>>();
    scatter_kernel<<<(T_TOKENS + 255) / 256, 256>>>();
    gemm_kernel<32, true><<<dim3(N1 / 128, T_TOKENS / 128, E_NUM), 256, SMEM_SZ>>>(w13s);
    swiglu_quant_kernel<<<ENTRIES, 256>>>();
    gemm_kernel<22, false><<<dim3(H_DIM / 128, T_TOKENS / 128, E_NUM), 256, SMEM_SZ>>>(w2s);
    combine_kernel<<<T_TOKENS, 256>>>(shr, out);
}

// round 13
// speedup vs baseline: 1.2814x; 1.0327x over previous
#include <cuda_runtime.h>
#include <cuda_bf16.h>
#include <cstdint>
#include <math.h>

// ---------------- problem constants ----------------
#define T_TOKENS 8192
#define H_DIM    2048
#define I_DIM    1408
#define E_NUM    8
#define N1       (2*I_DIM)     // 2816
#define ENTRIES  (2*T_TOKENS)  // 16384 token-expert pairs

// ---------------- device scratch (static, no allocs) ----------------
__device__ __align__(16) __nv_bfloat16 g_xb  [(size_t)T_TOKENS * H_DIM];     // 33.6 MB
__device__ __align__(16) __nv_bfloat16 g_w13b[(size_t)E_NUM * N1 * H_DIM];   // 92.3 MB
__device__ __align__(16) __nv_bfloat16 g_w2b [(size_t)E_NUM * H_DIM * I_DIM];// 46.1 MB
__device__ __align__(16) __nv_bfloat16 g_ab  [(size_t)ENTRIES * I_DIM];      // 46.1 MB
__device__ __align__(16) float g_h[(size_t)ENTRIES * N1];                    // 184.5 MB
__device__ __align__(16) float g_y[(size_t)ENTRIES * H_DIM];                 // 134.2 MB
__device__ float g_xs[T_TOKENS];
__device__ float g_as[ENTRIES];
__device__ int   g_top_idx [T_TOKENS * 2];
__device__ float g_top_gate[T_TOKENS * 2];
__device__ int   g_counts[E_NUM];
__device__ int   g_bases [E_NUM];
__device__ int   g_cursor[E_NUM];
__device__ int   g_tok_list  [ENTRIES];
__device__ float g_entry_gate[ENTRIES];
__device__ int   g_entry_of  [ENTRIES];

// ---------------- helpers ----------------
__device__ __forceinline__ __nv_bfloat16 qb(float v, float s) {
    float r = rintf(v / s);                       // round-half-even == jnp.round
    r = fminf(fmaxf(r, -127.0f), 127.0f);
    return __float2bfloat16(r);                   // ints <=127 exact in bf16
}
__device__ __forceinline__ uint32_t smem_u32(const void* p) {
    uint32_t a;
    asm("{ .reg .u64 t; cvta.to.shared.u64 t, %1; cvt.u32.u64 %0, t; }" : "=r"(a) : "l"(p));
    return a;
}
__device__ __forceinline__ void ldm_x4(uint32_t* r, uint32_t addr) {
    asm volatile("ldmatrix.sync.aligned.m8n8.x4.shared.b16 {%0,%1,%2,%3}, [%4];"
        : "=r"(r[0]), "=r"(r[1]), "=r"(r[2]), "=r"(r[3]) : "r"(addr));
}
__device__ __forceinline__ void mma_bf16(float* d, const uint32_t* a, uint32_t b0, uint32_t b1) {
    asm volatile("mma.sync.aligned.m16n8k16.row.col.f32.bf16.bf16.f32 "
        "{%0,%1,%2,%3}, {%4,%5,%6,%7}, {%8,%9}, {%0,%1,%2,%3};"
        : "+f"(d[0]), "+f"(d[1]), "+f"(d[2]), "+f"(d[3])
        : "r"(a[0]), "r"(a[1]), "r"(a[2]), "r"(a[3]), "r"(b0), "r"(b1));
}
__device__ __forceinline__ void cp_async16(uint32_t dst, const void* src) {
    asm volatile("cp.async.cg.shared.global [%0], [%1], 16;"
                 :: "r"(dst), "l"(src) : "memory");
}

// ---------------- weight int32 -> bf16 ----------------
__global__ void __launch_bounds__(256) convb_kernel(const int* __restrict__ src,
                                                    int n8, int which) {
    int i = blockIdx.x * blockDim.x + threadIdx.x;
    if (i >= n8) return;
    const int4* s = reinterpret_cast<const int4*>(src) + 2 * (size_t)i;
    int4 a = s[0], b = s[1];
    __align__(16) __nv_bfloat16 o[8];
    o[0] = __float2bfloat16((float)a.x); o[1] = __float2bfloat16((float)a.y);
    o[2] = __float2bfloat16((float)a.z); o[3] = __float2bfloat16((float)a.w);
    o[4] = __float2bfloat16((float)b.x); o[5] = __float2bfloat16((float)b.y);
    o[6] = __float2bfloat16((float)b.z); o[7] = __float2bfloat16((float)b.w);
    __nv_bfloat16* dst = which ? g_w2b : g_w13b;
    *reinterpret_cast<uint4*>(dst + 8 * (size_t)i) = *reinterpret_cast<uint4*>(o);
}

// ---------------- init / prefix / scatter ----------------
__global__ void init_kernel() {
    if (threadIdx.x < E_NUM) g_counts[threadIdx.x] = 0;
}
__global__ void prefix_kernel() {
    if (threadIdx.x == 0 && blockIdx.x == 0) {
        int acc = 0;
        for (int e = 0; e < E_NUM; e++) { g_bases[e] = acc; g_cursor[e] = acc; acc += g_counts[e]; }
    }
}
__global__ void __launch_bounds__(256) scatter_kernel() {
    int t = blockIdx.x * blockDim.x + threadIdx.x;
    if (t >= T_TOKENS) return;
#pragma unroll
    for (int k = 0; k < 2; k++) {
        int e = g_top_idx[2 * t + k];
        int pos = atomicAdd(&g_cursor[e], 1);
        g_tok_list[pos]   = t;
        g_entry_gate[pos] = g_top_gate[2 * t + k];
        g_entry_of[2 * t + k] = pos;
    }
}

// ---------------- gating + dynamic int8 quant (stored as bf16) ----------------
__global__ void __launch_bounds__(256) gate_quant_kernel(const float* __restrict__ x,
                                                         const float* __restrict__ gw) {
    int t = blockIdx.x;
    int tid = threadIdx.x, lane = tid & 31, warp = tid >> 5;
    const float* xr = x + (size_t)t * H_DIM;
    const float4* x4 = reinterpret_cast<const float4*>(xr);
    const float4* gw4 = reinterpret_cast<const float4*>(gw);

    float ps[E_NUM];
#pragma unroll
    for (int e = 0; e < E_NUM; e++) ps[e] = 0.0f;
    float pm = 0.0f;
#pragma unroll
    for (int it = 0; it < H_DIM / 4 / 256; it++) {    // 2 iterations
        int j4 = tid + it * 256;
        float4 v = x4[j4];
        pm = fmaxf(pm, fmaxf(fmaxf(fabsf(v.x), fabsf(v.y)),
                             fmaxf(fabsf(v.z), fabsf(v.w))));
#pragma unroll
        for (int e = 0; e < E_NUM; e++) {
            float4 g = gw4[e * (H_DIM / 4) + j4];
            ps[e] = fmaf(v.x, g.x, fmaf(v.y, g.y, fmaf(v.z, g.z, fmaf(v.w, g.w, ps[e]))));
        }
    }
#pragma unroll
    for (int e = 0; e < E_NUM; e++)
        for (int off = 16; off; off >>= 1)
            ps[e] += __shfl_down_sync(0xffffffffu, ps[e], off);
    for (int off = 16; off; off >>= 1)
        pm = fmaxf(pm, __shfl_down_sync(0xffffffffu, pm, off));

    __shared__ float sl[8][E_NUM];
    __shared__ float sm[8];
    __shared__ float sS;
    if (lane == 0) {
#pragma unroll
        for (int e = 0; e < E_NUM; e++) sl[warp][e] = ps[e];
        sm[warp] = pm;
    }
    __syncthreads();
    if (tid == 0) {
        float logit[E_NUM]; float mx = 0.0f;
#pragma unroll
        for (int e = 0; e < E_NUM; e++) {
            float l = 0.0f;
            for (int w = 0; w < 8; w++) l += sl[w][e];
            logit[e] = l;
        }
        for (int w = 0; w < 8; w++) mx = fmaxf(mx, sm[w]);
        float s = fmaxf(mx / 127.0f, 1e-8f);
        g_xs[t] = s; sS = s;
        int e0 = 0;
        for (int e = 1; e < E_NUM; e++) if (logit[e] > logit[e0]) e0 = e;
        int e1 = -1;
        for (int e = 0; e < E_NUM; e++)
            if (e != e0 && (e1 < 0 || logit[e] > logit[e1])) e1 = e;
        float g0 = 1.0f / (1.0f + expf(logit[e1] - logit[e0]));
        g_top_idx [2 * t]     = e0;
        g_top_idx [2 * t + 1] = e1;
        g_top_gate[2 * t]     = g0;
        g_top_gate[2 * t + 1] = 1.0f - g0;
        atomicAdd(&g_counts[e0], 1);
        atomicAdd(&g_counts[e1], 1);
    }
    __syncthreads();
    float s = sS;
    int w = tid;   // 2048/8 == 256 groups, exactly one per thread
    float4 v0 = x4[2 * w], v1 = x4[2 * w + 1];
    __align__(16) __nv_bfloat16 q[8] = {
        qb(v0.x, s), qb(v0.y, s), qb(v0.z, s), qb(v0.w, s),
        qb(v1.x, s), qb(v1.y, s), qb(v1.z, s), qb(v1.w, s)};
    *reinterpret_cast<uint4*>(g_xb + (size_t)t * H_DIM + 8 * w) = *reinterpret_cast<uint4*>(q);
}

// ---------------- HMMA grouped GEMM (bf16 operands, fp32 accum) ----------------
// CTA tile 128x128, K-chunk 64 bf16 (128B rows), 8 warps (2x4), warp tile 64x32.
// SMEM: 3-stage pipeline (16KB A + 16KB B per stage), single-sync mainloop.
template <int NKT, bool FC1>   // NKT = K/64
__global__ void __launch_bounds__(256, 2) gemm_kernel(const float* __restrict__ wscale) {
    const int e   = blockIdx.z;
    const int cnt = g_counts[e];
    const int m0  = blockIdx.y * 128;
    if (m0 >= cnt) return;
    const int n0  = blockIdx.x * 128;
    const int base = g_bases[e];
    const int NTOT = FC1 ? N1 : H_DIM;

    extern __shared__ char smem_raw[];
    char* smem = (char*)(((uintptr_t)smem_raw + 1023) & ~(uintptr_t)1023);
    const uint32_t sbase = smem_u32(smem);
    // stage s: A at s*32768, B at s*32768 + 16384

    const int tid  = threadIdx.x;
    const int wid  = tid >> 5;
    const int lane = tid & 31;

    // ---- cp.async mapping: thread t -> row t>>1, 16B chunks (t&1)*4 + 0..3 ----
    const int lrow = tid >> 1;
    const int lc0  = (tid & 1) * 4;
    int am = m0 + lrow; if (am > cnt - 1) am = cnt - 1;
    const char* a_src;
    const char* b_src;
    if (FC1) {
        a_src = (const char*)(g_xb + (size_t)g_tok_list[base + am] * H_DIM);
        b_src = (const char*)(g_w13b + ((size_t)e * N1 + n0 + lrow) * H_DIM);
    } else {
        a_src = (const char*)(g_ab + (size_t)(base + am) * I_DIM);
        b_src = (const char*)(g_w2b + ((size_t)e * H_DIM + n0 + lrow) * I_DIM);
    }
    uint32_t dsto[4];
#pragma unroll
    for (int j = 0; j < 4; j++)
        dsto[j] = (uint32_t)(lrow * 128 + 16 * ((lc0 + j) ^ (lrow & 7)));

    auto issue = [&](int kt, int buf) {
        uint32_t abuf = sbase + (uint32_t)buf * 32768u;
        uint32_t bbuf = abuf + 16384u;
        const char* as = a_src + kt * 128;   // 64 bf16 = 128 bytes per chunk
        const char* bs = b_src + kt * 128;
#pragma unroll
        for (int j = 0; j < 4; j++) {
            cp_async16(abuf + dsto[j], as + (lc0 + j) * 16);
            cp_async16(bbuf + dsto[j], bs + (lc0 + j) * 16);
        }
        asm volatile("cp.async.commit_group;" ::: "memory");
    };

    // ---- fragment addressing (canonical ldmatrix.x4 patterns) ----
    const int wm = (wid >> 2) * 64;   // warp M offset: 0 or 64
    const int wn = (wid & 3) * 32;    // warp N offset: 0,32,64,96

    uint32_t a_off[4]; int a_s[4];
    const int a_hi = lane >> 4;                // 16B half of k16 step
#pragma unroll
    for (int ma = 0; ma < 4; ma++) {
        int r = wm + ma * 16 + (lane & 15);
        a_off[ma] = (uint32_t)(r * 128);
        a_s[ma]   = r & 7;
    }
    uint32_t b_off[2]; int b_s[2];
    const int b_hi = (lane >> 3) & 1;
#pragma unroll
    for (int p = 0; p < 2; p++) {
        int r = wn + p * 16 + (lane & 7) + ((lane >> 4) << 3);
        b_off[p] = (uint32_t)(r * 128);
        b_s[p]   = r & 7;
    }

    float acc[4][4][4];
#pragma unroll
    for (int i = 0; i < 4; i++)
#pragma unroll
        for (int j = 0; j < 4; j++)
#pragma unroll
            for (int k = 0; k < 4; k++) acc[i][j][k] = 0.0f;

    // prologue: 2 stages in flight
    issue(0, 0);
    if (NKT > 1) issue(1, 1);

    int buf = 0;       // buffer holding chunk kt
    int nbuf = 2;      // buffer to fill with chunk kt+2
    for (int kt = 0; kt < NKT; kt++) {
        if (kt + 1 < NKT)
            asm volatile("cp.async.wait_group 1;" ::: "memory");
        else
            asm volatile("cp.async.wait_group 0;" ::: "memory");
        __syncthreads();   // single barrier: orders last iter's reads before nbuf writes

        // refill early: nbuf == buffer computed at kt-1, proven drained by the barrier
        if (kt + 2 < NKT) issue(kt + 2, nbuf);

        uint32_t abuf = sbase + (uint32_t)buf * 32768u;
        uint32_t bbuf = abuf + 16384u;
#pragma unroll
        for (int ks = 0; ks < 4; ks++) {       // 4 x k16 per 64-elem chunk
            uint32_t af[4][4];
#pragma unroll
            for (int ma = 0; ma < 4; ma++)
                ldm_x4(af[ma], abuf + a_off[ma] + 16u * (uint32_t)((2 * ks + a_hi) ^ a_s[ma]));
            uint32_t bf[2][4];
#pragma unroll
            for (int p = 0; p < 2; p++)
                ldm_x4(bf[p], bbuf + b_off[p] + 16u * (uint32_t)((2 * ks + b_hi) ^ b_s[p]));
#pragma unroll
            for (int ma = 0; ma < 4; ma++) {
#pragma unroll
                for (int na = 0; na < 4; na++) {
                    int p = na >> 1, q = (na & 1) * 2;
                    mma_bf16(acc[ma][na], af[ma], bf[p][q], bf[p][q + 1]);
                }
            }
        }
        buf  = (buf  == 2) ? 0 : buf  + 1;
        nbuf = (nbuf == 2) ? 0 : nbuf + 1;
    }

    // ---- epilogue: scale and store ----
    const int qn = (lane & 3) * 2;
    float2 wsc[4];
#pragma unroll
    for (int na = 0; na < 4; na++)
        wsc[na] = *reinterpret_cast<const float2*>(&wscale[e * NTOT + n0 + wn + na * 8 + qn]);

#pragma unroll
    for (int ma = 0; ma < 4; ma++) {
#pragma unroll
        for (int h = 0; h < 2; h++) {
            int m = m0 + wm + ma * 16 + (lane >> 2) + h * 8;
            if (m >= cnt) continue;
            int entry = base + m;
            float fsc;
            float* orow;
            if (FC1) { fsc = g_xs[g_tok_list[entry]]; orow = g_h + (size_t)entry * N1; }
            else     { fsc = g_as[entry] * g_entry_gate[entry]; orow = g_y + (size_t)entry * H_DIM; }
#pragma unroll
            for (int na = 0; na < 4; na++) {
                float2 o;
                o.x = acc[ma][na][2 * h + 0] * fsc * wsc[na].x;
                o.y = acc[ma][na][2 * h + 1] * fsc * wsc[na].y;
                *reinterpret_cast<float2*>(orow + n0 + wn + na * 8 + qn) = o;
            }
        }
    }
}

// ---------------- SwiGLU + dynamic int8 re-quant (stored as bf16) ----------------
__global__ void __launch_bounds__(256) swiglu_quant_kernel() {
    int entry = blockIdx.x;
    int tid = threadIdx.x, lane = tid & 31, warp = tid >> 5;
    const float* hr = g_h + (size_t)entry * N1;

    __shared__ __align__(16) float a_sh[I_DIM];
    __shared__ float wmax[8];
    __shared__ float sS;

    float pm = 0.0f;
    for (int i = tid; i < I_DIM; i += 256) {
        float h1 = hr[i];
        float h2 = hr[i + I_DIM];
        float a = h1 / (1.0f + expf(-h1)) * h2;
        a_sh[i] = a;
        pm = fmaxf(pm, fabsf(a));
    }
    for (int off = 16; off; off >>= 1)
        pm = fmaxf(pm, __shfl_down_sync(0xffffffffu, pm, off));
    if (lane == 0) wmax[warp] = pm;
    __syncthreads();
    if (tid == 0) {
        float mx = 0.0f;
        for (int w = 0; w < 8; w++) mx = fmaxf(mx, wmax[w]);
        float s = fmaxf(mx / 127.0f, 1e-8f);
        g_as[entry] = s; sS = s;
    }
    __syncthreads();
    float s = sS;
    if (tid < I_DIM / 8) {   // 176 groups of 8
        float4 v0 = *reinterpret_cast<const float4*>(&a_sh[8 * tid]);
        float4 v1 = *reinterpret_cast<const float4*>(&a_sh[8 * tid + 4]);
        __align__(16) __nv_bfloat16 q[8] = {
            qb(v0.x, s), qb(v0.y, s), qb(v0.z, s), qb(v0.w, s),
            qb(v1.x, s), qb(v1.y, s), qb(v1.z, s), qb(v1.w, s)};
        *reinterpret_cast<uint4*>(g_ab + (size_t)entry * I_DIM + 8 * tid) =
            *reinterpret_cast<uint4*>(q);
    }
}

// ---------------- combine ----------------
__global__ void __launch_bounds__(256) combine_kernel(const float* __restrict__ shared_out,
                                                      float* __restrict__ out) {
    int t = blockIdx.x;
    int p0 = g_entry_of[2 * t];
    int p1 = g_entry_of[2 * t + 1];
    const float4* s4 = reinterpret_cast<const float4*>(shared_out + (size_t)t * H_DIM);
    const float4* y0 = reinterpret_cast<const float4*>(g_y + (size_t)p0 * H_DIM);
    const float4* y1 = reinterpret_cast<const float4*>(g_y + (size_t)p1 * H_DIM);
    float4* o4 = reinterpret_cast<float4*>(out + (size_t)t * H_DIM);
    for (int w = threadIdx.x; w < H_DIM / 4; w += 256) {
        float4 a = s4[w], b = y0[w], c = y1[w];
        float4 r;
        r.x = a.x + b.x + c.x; r.y = a.y + b.y + c.y;
        r.z = a.z + b.z + c.z; r.w = a.w + b.w + c.w;
        o4[w] = r;
    }
}

// ---------------- launch ----------------
extern "C" void kernel_launch(void* const* d_in, const int* in_sizes, int n_in,
                              void* d_out, int out_size) {
    const float* x    = (const float*)d_in[0];
    const float* gw   = (const float*)d_in[1];
    const int*   w13q = (const int*)  d_in[2];
    const float* w13s = (const float*)d_in[3];
    const int*   w2q  = (const int*)  d_in[4];
    const float* w2s  = (const float*)d_in[5];
    const float* shr  = (const float*)d_in[6];
    float* out = (float*)d_out;

    const int SMEM_SZ = 1024 + 3 * 32768;   // align slack + 3-stage A/B
    static bool attr_set = false;
    if (!attr_set) {
        cudaFuncSetAttribute(gemm_kernel<32, true>,
                             cudaFuncAttributeMaxDynamicSharedMemorySize, SMEM_SZ);
        cudaFuncSetAttribute(gemm_kernel<22, false>,
                             cudaFuncAttributeMaxDynamicSharedMemorySize, SMEM_SZ);
        attr_set = true;
    }

    const int n8_w13 = E_NUM * N1 * H_DIM / 8;     // 5,767,168
    const int n8_w2  = E_NUM * H_DIM * I_DIM / 8;  // 2,883,584

    convb_kernel<<<(n8_w13 + 255) / 256, 256>>>(w13q, n8_w13, 0);
    convb_kernel<<<(n8_w2  + 255) / 256, 256>>>(w2q,  n8_w2,  1);
    init_kernel<<<1, 32>>>();
    gate_quant_kernel<<<T_TOKENS, 256>>>(x, gw);
    prefix_kernel<<<1, 32>>>();
    scatter_kernel<<<(T_TOKENS + 255) / 256, 256>>>();
    gemm_kernel<32, true><<<dim3(N1 / 128, T_TOKENS / 128, E_NUM), 256, SMEM_SZ>>>(w13s);
    swiglu_quant_kernel<<<ENTRIES, 256>>>();
    gemm_kernel<22, false><<<dim3(H_DIM / 128, T_TOKENS / 128, E_NUM), 256, SMEM_SZ>>>(w2s);
    combine_kernel<<<T_TOKENS, 256>>>(shr, out);
}

// round 15
// speedup vs baseline: 1.3097x; 1.0221x over previous
#include <cuda_runtime.h>
#include <cuda_bf16.h>
#include <cstdint>
#include <math.h>

// ---------------- problem constants ----------------
#define T_TOKENS 8192
#define H_DIM    2048
#define I_DIM    1408
#define E_NUM    8
#define N1       (2*I_DIM)     // 2816
#define ENTRIES  (2*T_TOKENS)  // 16384 token-expert pairs

// ---------------- device scratch (static, no allocs) ----------------
__device__ __align__(16) __nv_bfloat16 g_xb  [(size_t)T_TOKENS * H_DIM];     // 33.6 MB
__device__ __align__(16) __nv_bfloat16 g_w13b[(size_t)E_NUM * N1 * H_DIM];   // 92.3 MB
__device__ __align__(16) __nv_bfloat16 g_w2b [(size_t)E_NUM * H_DIM * I_DIM];// 46.1 MB
__device__ __align__(16) __nv_bfloat16 g_ab  [(size_t)ENTRIES * I_DIM];      // 46.1 MB
__device__ __align__(16) float g_h[(size_t)ENTRIES * N1];                    // 184.5 MB
__device__ __align__(16) float g_y[(size_t)ENTRIES * H_DIM];                 // 134.2 MB
__device__ float g_xs[T_TOKENS];
__device__ float g_as[ENTRIES];
__device__ int   g_top_idx [T_TOKENS * 2];
__device__ float g_top_gate[T_TOKENS * 2];
__device__ int   g_counts[E_NUM];
__device__ int   g_bases [E_NUM];
__device__ int   g_cursor[E_NUM];
__device__ int   g_tok_list  [ENTRIES];
__device__ float g_entry_gate[ENTRIES];
__device__ int   g_entry_of  [ENTRIES];

// ---------------- helpers ----------------
__device__ __forceinline__ __nv_bfloat16 qb(float v, float s) {
    float r = rintf(v / s);                       // round-half-even == jnp.round
    r = fminf(fmaxf(r, -127.0f), 127.0f);
    return __float2bfloat16(r);                   // ints <=127 exact in bf16
}
__device__ __forceinline__ uint32_t smem_u32(const void* p) {
    uint32_t a;
    asm("{ .reg .u64 t; cvta.to.shared.u64 t, %1; cvt.u32.u64 %0, t; }" : "=r"(a) : "l"(p));
    return a;
}
__device__ __forceinline__ void ldm_x4(uint32_t* r, uint32_t addr) {
    asm volatile("ldmatrix.sync.aligned.m8n8.x4.shared.b16 {%0,%1,%2,%3}, [%4];"
        : "=r"(r[0]), "=r"(r[1]), "=r"(r[2]), "=r"(r[3]) : "r"(addr));
}
__device__ __forceinline__ void mma_bf16(float* d, const uint32_t* a, uint32_t b0, uint32_t b1) {
    asm volatile("mma.sync.aligned.m16n8k16.row.col.f32.bf16.bf16.f32 "
        "{%0,%1,%2,%3}, {%4,%5,%6,%7}, {%8,%9}, {%0,%1,%2,%3};"
        : "+f"(d[0]), "+f"(d[1]), "+f"(d[2]), "+f"(d[3])
        : "r"(a[0]), "r"(a[1]), "r"(a[2]), "r"(a[3]), "r"(b0), "r"(b1));
}
__device__ __forceinline__ void cp_async16(uint32_t dst, const void* src) {
    asm volatile("cp.async.cg.shared.global [%0], [%1], 16;"
                 :: "r"(dst), "l"(src) : "memory");
}
__device__ __forceinline__ float sigmoid_fast(float x) {
    return 1.0f / (1.0f + __expf(-x));            // single MUFU EX2 path
}

// ---------------- weight int32 -> bf16 (both tensors, one launch) ----------------
__global__ void __launch_bounds__(256) convb_all_kernel(const int* __restrict__ w13,
                                                        const int* __restrict__ w2,
                                                        int n13, int ntot) {
    int i = blockIdx.x * blockDim.x + threadIdx.x;
    if (i >= ntot) return;
    const int* src;
    __nv_bfloat16* dst;
    int idx;
    if (i < n13) { src = w13; dst = g_w13b; idx = i; }
    else         { src = w2;  dst = g_w2b;  idx = i - n13; }
    const int4* s = reinterpret_cast<const int4*>(src) + 2 * (size_t)idx;
    int4 a = s[0], b = s[1];
    __align__(16) __nv_bfloat16 o[8];
    o[0] = __float2bfloat16((float)a.x); o[1] = __float2bfloat16((float)a.y);
    o[2] = __float2bfloat16((float)a.z); o[3] = __float2bfloat16((float)a.w);
    o[4] = __float2bfloat16((float)b.x); o[5] = __float2bfloat16((float)b.y);
    o[6] = __float2bfloat16((float)b.z); o[7] = __float2bfloat16((float)b.w);
    *reinterpret_cast<uint4*>(dst + 8 * (size_t)idx) = *reinterpret_cast<uint4*>(o);
}

// ---------------- init / prefix / scatter ----------------
__global__ void init_kernel() {
    if (threadIdx.x < E_NUM) g_counts[threadIdx.x] = 0;
}
__global__ void prefix_kernel() {
    if (threadIdx.x == 0 && blockIdx.x == 0) {
        int acc = 0;
        for (int e = 0; e < E_NUM; e++) { g_bases[e] = acc; g_cursor[e] = acc; acc += g_counts[e]; }
    }
}
__global__ void __launch_bounds__(256) scatter_kernel() {
    int t = blockIdx.x * blockDim.x + threadIdx.x;
    if (t >= T_TOKENS) return;
#pragma unroll
    for (int k = 0; k < 2; k++) {
        int e = g_top_idx[2 * t + k];
        int pos = atomicAdd(&g_cursor[e], 1);
        g_tok_list[pos]   = t;
        g_entry_gate[pos] = g_top_gate[2 * t + k];
        g_entry_of[2 * t + k] = pos;
    }
}

// ---------------- gating + dynamic int8 quant (stored as bf16) ----------------
__global__ void __launch_bounds__(256) gate_quant_kernel(const float* __restrict__ x,
                                                         const float* __restrict__ gw) {
    int t = blockIdx.x;
    int tid = threadIdx.x, lane = tid & 31, warp = tid >> 5;
    const float* xr = x + (size_t)t * H_DIM;
    const float4* x4 = reinterpret_cast<const float4*>(xr);
    const float4* gw4 = reinterpret_cast<const float4*>(gw);

    float ps[E_NUM];
#pragma unroll
    for (int e = 0; e < E_NUM; e++) ps[e] = 0.0f;
    float pm = 0.0f;
#pragma unroll
    for (int it = 0; it < H_DIM / 4 / 256; it++) {    // 2 iterations
        int j4 = tid + it * 256;
        float4 v = x4[j4];
        pm = fmaxf(pm, fmaxf(fmaxf(fabsf(v.x), fabsf(v.y)),
                             fmaxf(fabsf(v.z), fabsf(v.w))));
#pragma unroll
        for (int e = 0; e < E_NUM; e++) {
            float4 g = gw4[e * (H_DIM / 4) + j4];
            ps[e] = fmaf(v.x, g.x, fmaf(v.y, g.y, fmaf(v.z, g.z, fmaf(v.w, g.w, ps[e]))));
        }
    }
#pragma unroll
    for (int e = 0; e < E_NUM; e++)
        for (int off = 16; off; off >>= 1)
            ps[e] += __shfl_down_sync(0xffffffffu, ps[e], off);
    for (int off = 16; off; off >>= 1)
        pm = fmaxf(pm, __shfl_down_sync(0xffffffffu, pm, off));

    __shared__ float sl[8][E_NUM];
    __shared__ float sm[8];
    __shared__ float sS;
    if (lane == 0) {
#pragma unroll
        for (int e = 0; e < E_NUM; e++) sl[warp][e] = ps[e];
        sm[warp] = pm;
    }
    __syncthreads();
    if (tid == 0) {
        float logit[E_NUM]; float mx = 0.0f;
#pragma unroll
        for (int e = 0; e < E_NUM; e++) {
            float l = 0.0f;
            for (int w = 0; w < 8; w++) l += sl[w][e];
            logit[e] = l;
        }
        for (int w = 0; w < 8; w++) mx = fmaxf(mx, sm[w]);
        float s = fmaxf(mx / 127.0f, 1e-8f);
        g_xs[t] = s; sS = s;
        int e0 = 0;
        for (int e = 1; e < E_NUM; e++) if (logit[e] > logit[e0]) e0 = e;
        int e1 = -1;
        for (int e = 0; e < E_NUM; e++)
            if (e != e0 && (e1 < 0 || logit[e] > logit[e1])) e1 = e;
        float g0 = 1.0f / (1.0f + __expf(logit[e1] - logit[e0]));
        g_top_idx [2 * t]     = e0;
        g_top_idx [2 * t + 1] = e1;
        g_top_gate[2 * t]     = g0;
        g_top_gate[2 * t + 1] = 1.0f - g0;
        atomicAdd(&g_counts[e0], 1);
        atomicAdd(&g_counts[e1], 1);
    }
    __syncthreads();
    float s = sS;
    int w = tid;   // 2048/8 == 256 groups, exactly one per thread
    float4 v0 = x4[2 * w], v1 = x4[2 * w + 1];
    __align__(16) __nv_bfloat16 q[8] = {
        qb(v0.x, s), qb(v0.y, s), qb(v0.z, s), qb(v0.w, s),
        qb(v1.x, s), qb(v1.y, s), qb(v1.z, s), qb(v1.w, s)};
    *reinterpret_cast<uint4*>(g_xb + (size_t)t * H_DIM + 8 * w) = *reinterpret_cast<uint4*>(q);
}

// ---------------- HMMA grouped GEMM (bf16 operands, fp32 accum) ----------------
// CTA tile 128x128, K-chunk 64 bf16 (128B rows), 8 warps (2x4), warp tile 64x32.
// SMEM: 3-stage pipeline (16KB A + 16KB B per stage), single-sync mainloop.
template <int NKT, bool FC1>   // NKT = K/64
__global__ void __launch_bounds__(256, 2) gemm_kernel(const float* __restrict__ wscale) {
    const int e   = blockIdx.z;
    const int cnt = g_counts[e];
    const int m0  = blockIdx.y * 128;
    if (m0 >= cnt) return;
    const int n0  = blockIdx.x * 128;
    const int base = g_bases[e];
    const int NTOT = FC1 ? N1 : H_DIM;

    extern __shared__ char smem_raw[];
    char* smem = (char*)(((uintptr_t)smem_raw + 1023) & ~(uintptr_t)1023);
    const uint32_t sbase = smem_u32(smem);
    // stage s: A at s*32768, B at s*32768 + 16384

    const int tid  = threadIdx.x;
    const int wid  = tid >> 5;
    const int lane = tid & 31;

    // ---- cp.async mapping: thread t -> row t>>1, 16B chunks (t&1)*4 + 0..3 ----
    const int lrow = tid >> 1;
    const int lc0  = (tid & 1) * 4;
    int am = m0 + lrow; if (am > cnt - 1) am = cnt - 1;
    const char* a_src;
    const char* b_src;
    if (FC1) {
        a_src = (const char*)(g_xb + (size_t)g_tok_list[base + am] * H_DIM);
        b_src = (const char*)(g_w13b + ((size_t)e * N1 + n0 + lrow) * H_DIM);
    } else {
        a_src = (const char*)(g_ab + (size_t)(base + am) * I_DIM);
        b_src = (const char*)(g_w2b + ((size_t)e * H_DIM + n0 + lrow) * I_DIM);
    }
    uint32_t dsto[4];
#pragma unroll
    for (int j = 0; j < 4; j++)
        dsto[j] = (uint32_t)(lrow * 128 + 16 * ((lc0 + j) ^ (lrow & 7)));

    auto issue = [&](int kt, int buf) {
        uint32_t abuf = sbase + (uint32_t)buf * 32768u;
        uint32_t bbuf = abuf + 16384u;
        const char* as = a_src + kt * 128;   // 64 bf16 = 128 bytes per chunk
        const char* bs = b_src + kt * 128;
#pragma unroll
        for (int j = 0; j < 4; j++) {
            cp_async16(abuf + dsto[j], as + (lc0 + j) * 16);
            cp_async16(bbuf + dsto[j], bs + (lc0 + j) * 16);
        }
        asm volatile("cp.async.commit_group;" ::: "memory");
    };

    // ---- fragment addressing (canonical ldmatrix.x4 patterns) ----
    const int wm = (wid >> 2) * 64;   // warp M offset: 0 or 64
    const int wn = (wid & 3) * 32;    // warp N offset: 0,32,64,96

    uint32_t a_off[4]; int a_s[4];
    const int a_hi = lane >> 4;                // 16B half of k16 step
#pragma unroll
    for (int ma = 0; ma < 4; ma++) {
        int r = wm + ma * 16 + (lane & 15);
        a_off[ma] = (uint32_t)(r * 128);
        a_s[ma]   = r & 7;
    }
    uint32_t b_off[2]; int b_s[2];
    const int b_hi = (lane >> 3) & 1;
#pragma unroll
    for (int p = 0; p < 2; p++) {
        int r = wn + p * 16 + (lane & 7) + ((lane >> 4) << 3);
        b_off[p] = (uint32_t)(r * 128);
        b_s[p]   = r & 7;
    }

    float acc[4][4][4];
#pragma unroll
    for (int i = 0; i < 4; i++)
#pragma unroll
        for (int j = 0; j < 4; j++)
#pragma unroll
            for (int k = 0; k < 4; k++) acc[i][j][k] = 0.0f;

    // prologue: 2 stages in flight
    issue(0, 0);
    if (NKT > 1) issue(1, 1);

    int buf = 0;       // buffer holding chunk kt
    int nbuf = 2;      // buffer to fill with chunk kt+2
    for (int kt = 0; kt < NKT; kt++) {
        if (kt + 1 < NKT)
            asm volatile("cp.async.wait_group 1;" ::: "memory");
        else
            asm volatile("cp.async.wait_group 0;" ::: "memory");
        __syncthreads();   // single barrier: orders last iter's reads before nbuf writes

        // refill early: nbuf == buffer computed at kt-1, proven drained by the barrier
        if (kt + 2 < NKT) issue(kt + 2, nbuf);

        uint32_t abuf = sbase + (uint32_t)buf * 32768u;
        uint32_t bbuf = abuf + 16384u;
#pragma unroll
        for (int ks = 0; ks < 4; ks++) {       // 4 x k16 per 64-elem chunk
            uint32_t af[4][4];
#pragma unroll
            for (int ma = 0; ma < 4; ma++)
                ldm_x4(af[ma], abuf + a_off[ma] + 16u * (uint32_t)((2 * ks + a_hi) ^ a_s[ma]));
            uint32_t bf[2][4];
#pragma unroll
            for (int p = 0; p < 2; p++)
                ldm_x4(bf[p], bbuf + b_off[p] + 16u * (uint32_t)((2 * ks + b_hi) ^ b_s[p]));
#pragma unroll
            for (int ma = 0; ma < 4; ma++) {
#pragma unroll
                for (int na = 0; na < 4; na++) {
                    int p = na >> 1, q = (na & 1) * 2;
                    mma_bf16(acc[ma][na], af[ma], bf[p][q], bf[p][q + 1]);
                }
            }
        }
        buf  = (buf  == 2) ? 0 : buf  + 1;
        nbuf = (nbuf == 2) ? 0 : nbuf + 1;
    }

    // ---- epilogue: scale and store ----
    const int qn = (lane & 3) * 2;
    float2 wsc[4];
#pragma unroll
    for (int na = 0; na < 4; na++)
        wsc[na] = *reinterpret_cast<const float2*>(&wscale[e * NTOT + n0 + wn + na * 8 + qn]);

#pragma unroll
    for (int ma = 0; ma < 4; ma++) {
#pragma unroll
        for (int h = 0; h < 2; h++) {
            int m = m0 + wm + ma * 16 + (lane >> 2) + h * 8;
            if (m >= cnt) continue;
            int entry = base + m;
            float fsc;
            float* orow;
            if (FC1) { fsc = g_xs[g_tok_list[entry]]; orow = g_h + (size_t)entry * N1; }
            else     { fsc = g_as[entry] * g_entry_gate[entry]; orow = g_y + (size_t)entry * H_DIM; }
#pragma unroll
            for (int na = 0; na < 4; na++) {
                float2 o;
                o.x = acc[ma][na][2 * h + 0] * fsc * wsc[na].x;
                o.y = acc[ma][na][2 * h + 1] * fsc * wsc[na].y;
                *reinterpret_cast<float2*>(orow + n0 + wn + na * 8 + qn) = o;
            }
        }
    }
}

// ---------------- SwiGLU + dynamic int8 re-quant (stored as bf16) ----------------
__global__ void __launch_bounds__(256) swiglu_quant_kernel() {
    int entry = blockIdx.x;
    int tid = threadIdx.x, lane = tid & 31, warp = tid >> 5;
    const float* hr = g_h + (size_t)entry * N1;

    __shared__ __align__(16) float a_sh[I_DIM];
    __shared__ float wmax[8];
    __shared__ float sS;

    float pm = 0.0f;
    for (int w4 = tid; w4 < I_DIM / 4; w4 += 256) {   // 352 float4 groups
        float4 h1 = *reinterpret_cast<const float4*>(hr + 4 * w4);
        float4 h2 = *reinterpret_cast<const float4*>(hr + I_DIM + 4 * w4);
        float4 a;
        a.x = h1.x * sigmoid_fast(h1.x) * h2.x;
        a.y = h1.y * sigmoid_fast(h1.y) * h2.y;
        a.z = h1.z * sigmoid_fast(h1.z) * h2.z;
        a.w = h1.w * sigmoid_fast(h1.w) * h2.w;
        *reinterpret_cast<float4*>(&a_sh[4 * w4]) = a;
        pm = fmaxf(pm, fmaxf(fmaxf(fabsf(a.x), fabsf(a.y)),
                             fmaxf(fabsf(a.z), fabsf(a.w))));
    }
    for (int off = 16; off; off >>= 1)
        pm = fmaxf(pm, __shfl_down_sync(0xffffffffu, pm, off));
    if (lane == 0) wmax[warp] = pm;
    __syncthreads();
    if (tid == 0) {
        float mx = 0.0f;
        for (int w = 0; w < 8; w++) mx = fmaxf(mx, wmax[w]);
        float s = fmaxf(mx / 127.0f, 1e-8f);
        g_as[entry] = s; sS = s;
    }
    __syncthreads();
    float s = sS;
    if (tid < I_DIM / 8) {   // 176 groups of 8
        float4 v0 = *reinterpret_cast<const float4*>(&a_sh[8 * tid]);
        float4 v1 = *reinterpret_cast<const float4*>(&a_sh[8 * tid + 4]);
        __align__(16) __nv_bfloat16 q[8] = {
            qb(v0.x, s), qb(v0.y, s), qb(v0.z, s), qb(v0.w, s),
            qb(v1.x, s), qb(v1.y, s), qb(v1.z, s), qb(v1.w, s)};
        *reinterpret_cast<uint4*>(g_ab + (size_t)entry * I_DIM + 8 * tid) =
            *reinterpret_cast<uint4*>(q);
    }
}

// ---------------- combine ----------------
__global__ void __launch_bounds__(256) combine_kernel(const float* __restrict__ shared_out,
                                                      float* __restrict__ out) {
    int t = blockIdx.x;
    int p0 = g_entry_of[2 * t];
    int p1 = g_entry_of[2 * t + 1];
    const float4* s4 = reinterpret_cast<const float4*>(shared_out + (size_t)t * H_DIM);
    const float4* y0 = reinterpret_cast<const float4*>(g_y + (size_t)p0 * H_DIM);
    const float4* y1 = reinterpret_cast<const float4*>(g_y + (size_t)p1 * H_DIM);
    float4* o4 = reinterpret_cast<float4*>(out + (size_t)t * H_DIM);
    for (int w = threadIdx.x; w < H_DIM / 4; w += 256) {
        float4 a = s4[w], b = y0[w], c = y1[w];
        float4 r;
        r.x = a.x + b.x + c.x; r.y = a.y + b.y + c.y;
        r.z = a.z + b.z + c.z; r.w = a.w + b.w + c.w;
        o4[w] = r;
    }
}

// ---------------- launch ----------------
extern "C" void kernel_launch(void* const* d_in, const int* in_sizes, int n_in,
                              void* d_out, int out_size) {
    const float* x    = (const float*)d_in[0];
    const float* gw   = (const float*)d_in[1];
    const int*   w13q = (const int*)  d_in[2];
    const float* w13s = (const float*)d_in[3];
    const int*   w2q  = (const int*)  d_in[4];
    const float* w2s  = (const float*)d_in[5];
    const float* shr  = (const float*)d_in[6];
    float* out = (float*)d_out;

    const int SMEM_SZ = 1024 + 3 * 32768;   // align slack + 3-stage A/B
    static bool attr_set = false;
    if (!attr_set) {
        cudaFuncSetAttribute(gemm_kernel<32, true>,
                             cudaFuncAttributeMaxDynamicSharedMemorySize, SMEM_SZ);
        cudaFuncSetAttribute(gemm_kernel<22, false>,
                             cudaFuncAttributeMaxDynamicSharedMemorySize, SMEM_SZ);
        attr_set = true;
    }

    const int n8_w13 = E_NUM * N1 * H_DIM / 8;     // 5,767,168
    const int n8_w2  = E_NUM * H_DIM * I_DIM / 8;  // 2,883,584
    const int n8_tot = n8_w13 + n8_w2;

    convb_all_kernel<<<(n8_tot + 255) / 256, 256>>>(w13q, w2q, n8_w13, n8_tot);
    init_kernel<<<1, 32>>>();
    gate_quant_kernel<<<T_TOKENS, 256>>>(x, gw);
    prefix_kernel<<<1, 32>>>();
    scatter_kernel<<<(T_TOKENS + 255) / 256, 256>>>();
    gemm_kernel<32, true><<<dim3(N1 / 128, T_TOKENS / 128, E_NUM), 256, SMEM_SZ>>>(w13s);
    swiglu_quant_kernel<<<ENTRIES, 256>>>();
    gemm_kernel<22, false><<<dim3(H_DIM / 128, T_TOKENS / 128, E_NUM), 256, SMEM_SZ>>>(w2s);
    combine_kernel<<<T_TOKENS, 256>>>(shr, out);
}

// round 17
// speedup vs baseline: 1.3126x; 1.0022x over previous
#include <cuda_runtime.h>
#include <cuda_bf16.h>
#include <cstdint>
#include <math.h>

// ---------------- problem constants ----------------
#define T_TOKENS 8192
#define H_DIM    2048
#define I_DIM    1408
#define E_NUM    8
#define N1       (2*I_DIM)     // 2816
#define ENTRIES  (2*T_TOKENS)  // 16384 token-expert pairs

// ---------------- device scratch (static, no allocs) ----------------
__device__ __align__(16) __nv_bfloat16 g_xb  [(size_t)T_TOKENS * H_DIM];     // 33.6 MB
__device__ __align__(16) __nv_bfloat16 g_w13b[(size_t)E_NUM * N1 * H_DIM];   // 92.3 MB
__device__ __align__(16) __nv_bfloat16 g_w2b [(size_t)E_NUM * H_DIM * I_DIM];// 46.1 MB
__device__ __align__(16) __nv_bfloat16 g_ab  [(size_t)ENTRIES * I_DIM];      // 46.1 MB
__device__ __align__(16) float g_h[(size_t)ENTRIES * N1];                    // 184.5 MB
__device__ __align__(16) float g_y[(size_t)ENTRIES * H_DIM];                 // 134.2 MB
__device__ float g_xs[T_TOKENS];
__device__ float g_as[ENTRIES];
__device__ int   g_top_idx [T_TOKENS * 2];
__device__ float g_top_gate[T_TOKENS * 2];
__device__ int   g_counts[E_NUM];
__device__ int   g_bases [E_NUM];
__device__ int   g_cursor[E_NUM];
__device__ int   g_tok_list  [ENTRIES];
__device__ float g_entry_gate[ENTRIES];
__device__ int   g_entry_of  [ENTRIES];

// ---------------- side stream for graph fork/join (created pre-baseline) ----------------
static cudaStream_t g_s2;
static cudaEvent_t  g_ev0, g_ev1;
namespace {
struct StreamInit {
    StreamInit() {
        cudaStreamCreateWithFlags(&g_s2, cudaStreamNonBlocking);
        cudaEventCreateWithFlags(&g_ev0, cudaEventDisableTiming);
        cudaEventCreateWithFlags(&g_ev1, cudaEventDisableTiming);
    }
};
static StreamInit s_stream_init;
}

// ---------------- helpers ----------------
__device__ __forceinline__ __nv_bfloat16 qb(float v, float s) {
    float r = rintf(v / s);                       // round-half-even == jnp.round
    r = fminf(fmaxf(r, -127.0f), 127.0f);
    return __float2bfloat16(r);                   // ints <=127 exact in bf16
}
__device__ __forceinline__ uint32_t smem_u32(const void* p) {
    uint32_t a;
    asm("{ .reg .u64 t; cvta.to.shared.u64 t, %1; cvt.u32.u64 %0, t; }" : "=r"(a) : "l"(p));
    return a;
}
__device__ __forceinline__ void ldm_x4(uint32_t* r, uint32_t addr) {
    asm volatile("ldmatrix.sync.aligned.m8n8.x4.shared.b16 {%0,%1,%2,%3}, [%4];"
        : "=r"(r[0]), "=r"(r[1]), "=r"(r[2]), "=r"(r[3]) : "r"(addr));
}
__device__ __forceinline__ void mma_bf16(float* d, const uint32_t* a, uint32_t b0, uint32_t b1) {
    asm volatile("mma.sync.aligned.m16n8k16.row.col.f32.bf16.bf16.f32 "
        "{%0,%1,%2,%3}, {%4,%5,%6,%7}, {%8,%9}, {%0,%1,%2,%3};"
        : "+f"(d[0]), "+f"(d[1]), "+f"(d[2]), "+f"(d[3])
        : "r"(a[0]), "r"(a[1]), "r"(a[2]), "r"(a[3]), "r"(b0), "r"(b1));
}
__device__ __forceinline__ void cp_async16(uint32_t dst, const void* src) {
    asm volatile("cp.async.cg.shared.global [%0], [%1], 16;"
                 :: "r"(dst), "l"(src) : "memory");
}
__device__ __forceinline__ float sigmoid_fast(float x) {
    return 1.0f / (1.0f + __expf(-x));            // single MUFU EX2 path
}

// ---------------- weight int32 -> bf16 (both tensors, one launch) ----------------
__global__ void __launch_bounds__(256) convb_all_kernel(const int* __restrict__ w13,
                                                        const int* __restrict__ w2,
                                                        int n13, int ntot) {
    int i = blockIdx.x * blockDim.x + threadIdx.x;
    if (i >= ntot) return;
    const int* src;
    __nv_bfloat16* dst;
    int idx;
    if (i < n13) { src = w13; dst = g_w13b; idx = i; }
    else         { src = w2;  dst = g_w2b;  idx = i - n13; }
    const int4* s = reinterpret_cast<const int4*>(src) + 2 * (size_t)idx;
    int4 a = s[0], b = s[1];
    __align__(16) __nv_bfloat16 o[8];
    o[0] = __float2bfloat16((float)a.x); o[1] = __float2bfloat16((float)a.y);
    o[2] = __float2bfloat16((float)a.z); o[3] = __float2bfloat16((float)a.w);
    o[4] = __float2bfloat16((float)b.x); o[5] = __float2bfloat16((float)b.y);
    o[6] = __float2bfloat16((float)b.z); o[7] = __float2bfloat16((float)b.w);
    *reinterpret_cast<uint4*>(dst + 8 * (size_t)idx) = *reinterpret_cast<uint4*>(o);
}

// ---------------- init / prefix / scatter ----------------
__global__ void init_kernel() {
    if (threadIdx.x < E_NUM) g_counts[threadIdx.x] = 0;
}
__global__ void prefix_kernel() {
    if (threadIdx.x == 0 && blockIdx.x == 0) {
        int acc = 0;
        for (int e = 0; e < E_NUM; e++) { g_bases[e] = acc; g_cursor[e] = acc; acc += g_counts[e]; }
    }
}
__global__ void __launch_bounds__(256) scatter_kernel() {
    int t = blockIdx.x * blockDim.x + threadIdx.x;
    if (t >= T_TOKENS) return;
#pragma unroll
    for (int k = 0; k < 2; k++) {
        int e = g_top_idx[2 * t + k];
        int pos = atomicAdd(&g_cursor[e], 1);
        g_tok_list[pos]   = t;
        g_entry_gate[pos] = g_top_gate[2 * t + k];
        g_entry_of[2 * t + k] = pos;
    }
}

// ---------------- gating + dynamic int8 quant (stored as bf16) ----------------
__global__ void __launch_bounds__(256) gate_quant_kernel(const float* __restrict__ x,
                                                         const float* __restrict__ gw) {
    int t = blockIdx.x;
    int tid = threadIdx.x, lane = tid & 31, warp = tid >> 5;
    const float* xr = x + (size_t)t * H_DIM;
    const float4* x4 = reinterpret_cast<const float4*>(xr);
    const float4* gw4 = reinterpret_cast<const float4*>(gw);

    float ps[E_NUM];
#pragma unroll
    for (int e = 0; e < E_NUM; e++) ps[e] = 0.0f;
    float pm = 0.0f;
#pragma unroll
    for (int it = 0; it < H_DIM / 4 / 256; it++) {    // 2 iterations
        int j4 = tid + it * 256;
        float4 v = x4[j4];
        pm = fmaxf(pm, fmaxf(fmaxf(fabsf(v.x), fabsf(v.y)),
                             fmaxf(fabsf(v.z), fabsf(v.w))));
#pragma unroll
        for (int e = 0; e < E_NUM; e++) {
            float4 g = gw4[e * (H_DIM / 4) + j4];
            ps[e] = fmaf(v.x, g.x, fmaf(v.y, g.y, fmaf(v.z, g.z, fmaf(v.w, g.w, ps[e]))));
        }
    }
#pragma unroll
    for (int e = 0; e < E_NUM; e++)
        for (int off = 16; off; off >>= 1)
            ps[e] += __shfl_down_sync(0xffffffffu, ps[e], off);
    for (int off = 16; off; off >>= 1)
        pm = fmaxf(pm, __shfl_down_sync(0xffffffffu, pm, off));

    __shared__ float sl[8][E_NUM];
    __shared__ float sm[8];
    __shared__ float sS;
    if (lane == 0) {
#pragma unroll
        for (int e = 0; e < E_NUM; e++) sl[warp][e] = ps[e];
        sm[warp] = pm;
    }
    __syncthreads();
    if (tid == 0) {
        float logit[E_NUM]; float mx = 0.0f;
#pragma unroll
        for (int e = 0; e < E_NUM; e++) {
            float l = 0.0f;
            for (int w = 0; w < 8; w++) l += sl[w][e];
            logit[e] = l;
        }
        for (int w = 0; w < 8; w++) mx = fmaxf(mx, sm[w]);
        float s = fmaxf(mx / 127.0f, 1e-8f);
        g_xs[t] = s; sS = s;
        int e0 = 0;
        for (int e = 1; e < E_NUM; e++) if (logit[e] > logit[e0]) e0 = e;
        int e1 = -1;
        for (int e = 0; e < E_NUM; e++)
            if (e != e0 && (e1 < 0 || logit[e] > logit[e1])) e1 = e;
        float g0 = 1.0f / (1.0f + __expf(logit[e1] - logit[e0]));
        g_top_idx [2 * t]     = e0;
        g_top_idx [2 * t + 1] = e1;
        g_top_gate[2 * t]     = g0;
        g_top_gate[2 * t + 1] = 1.0f - g0;
        atomicAdd(&g_counts[e0], 1);
        atomicAdd(&g_counts[e1], 1);
    }
    __syncthreads();
    float s = sS;
    int w = tid;   // 2048/8 == 256 groups, exactly one per thread
    float4 v0 = x4[2 * w], v1 = x4[2 * w + 1];
    __align__(16) __nv_bfloat16 q[8] = {
        qb(v0.x, s), qb(v0.y, s), qb(v0.z, s), qb(v0.w, s),
        qb(v1.x, s), qb(v1.y, s), qb(v1.z, s), qb(v1.w, s)};
    *reinterpret_cast<uint4*>(g_xb + (size_t)t * H_DIM + 8 * w) = *reinterpret_cast<uint4*>(q);
}

// ---------------- HMMA grouped GEMM (bf16 operands, fp32 accum) ----------------
// CTA tile 128x128, K-chunk 64 bf16 (128B rows), 8 warps (2x4), warp tile 64x32.
// SMEM: 3-stage pipeline (16KB A + 16KB B per stage), single-sync mainloop.
template <int NKT, bool FC1>   // NKT = K/64
__global__ void __launch_bounds__(256, 2) gemm_kernel(const float* __restrict__ wscale) {
    const int e   = blockIdx.z;
    const int cnt = g_counts[e];
    const int m0  = blockIdx.y * 128;
    if (m0 >= cnt) return;
    const int n0  = blockIdx.x * 128;
    const int base = g_bases[e];
    const int NTOT = FC1 ? N1 : H_DIM;

    extern __shared__ char smem_raw[];
    char* smem = (char*)(((uintptr_t)smem_raw + 1023) & ~(uintptr_t)1023);
    const uint32_t sbase = smem_u32(smem);
    // stage s: A at s*32768, B at s*32768 + 16384

    const int tid  = threadIdx.x;
    const int wid  = tid >> 5;
    const int lane = tid & 31;

    // ---- cp.async mapping: thread t -> row t>>1, 16B chunks (t&1)*4 + 0..3 ----
    const int lrow = tid >> 1;
    const int lc0  = (tid & 1) * 4;
    int am = m0 + lrow; if (am > cnt - 1) am = cnt - 1;
    const char* a_src;
    const char* b_src;
    if (FC1) {
        a_src = (const char*)(g_xb + (size_t)g_tok_list[base + am] * H_DIM);
        b_src = (const char*)(g_w13b + ((size_t)e * N1 + n0 + lrow) * H_DIM);
    } else {
        a_src = (const char*)(g_ab + (size_t)(base + am) * I_DIM);
        b_src = (const char*)(g_w2b + ((size_t)e * H_DIM + n0 + lrow) * I_DIM);
    }
    uint32_t dsto[4];
#pragma unroll
    for (int j = 0; j < 4; j++)
        dsto[j] = (uint32_t)(lrow * 128 + 16 * ((lc0 + j) ^ (lrow & 7)));

    auto issue = [&](int kt, int buf) {
        uint32_t abuf = sbase + (uint32_t)buf * 32768u;
        uint32_t bbuf = abuf + 16384u;
        const char* as = a_src + kt * 128;   // 64 bf16 = 128 bytes per chunk
        const char* bs = b_src + kt * 128;
#pragma unroll
        for (int j = 0; j < 4; j++) {
            cp_async16(abuf + dsto[j], as + (lc0 + j) * 16);
            cp_async16(bbuf + dsto[j], bs + (lc0 + j) * 16);
        }
        asm volatile("cp.async.commit_group;" ::: "memory");
    };

    // ---- fragment addressing (canonical ldmatrix.x4 patterns) ----
    const int wm = (wid >> 2) * 64;   // warp M offset: 0 or 64
    const int wn = (wid & 3) * 32;    // warp N offset: 0,32,64,96

    uint32_t a_off[4]; int a_s[4];
    const int a_hi = lane >> 4;                // 16B half of k16 step
#pragma unroll
    for (int ma = 0; ma < 4; ma++) {
        int r = wm + ma * 16 + (lane & 15);
        a_off[ma] = (uint32_t)(r * 128);
        a_s[ma]   = r & 7;
    }
    uint32_t b_off[2]; int b_s[2];
    const int b_hi = (lane >> 3) & 1;
#pragma unroll
    for (int p = 0; p < 2; p++) {
        int r = wn + p * 16 + (lane & 7) + ((lane >> 4) << 3);
        b_off[p] = (uint32_t)(r * 128);
        b_s[p]   = r & 7;
    }

    float acc[4][4][4];
#pragma unroll
    for (int i = 0; i < 4; i++)
#pragma unroll
        for (int j = 0; j < 4; j++)
#pragma unroll
            for (int k = 0; k < 4; k++) acc[i][j][k] = 0.0f;

    // prologue: 2 stages in flight
    issue(0, 0);
    if (NKT > 1) issue(1, 1);

    int buf = 0;       // buffer holding chunk kt
    int nbuf = 2;      // buffer to fill with chunk kt+2
    for (int kt = 0; kt < NKT; kt++) {
        if (kt + 1 < NKT)
            asm volatile("cp.async.wait_group 1;" ::: "memory");
        else
            asm volatile("cp.async.wait_group 0;" ::: "memory");
        __syncthreads();   // single barrier: orders last iter's reads before nbuf writes

        // refill early: nbuf == buffer computed at kt-1, proven drained by the barrier
        if (kt + 2 < NKT) issue(kt + 2, nbuf);

        uint32_t abuf = sbase + (uint32_t)buf * 32768u;
        uint32_t bbuf = abuf + 16384u;
#pragma unroll
        for (int ks = 0; ks < 4; ks++) {       // 4 x k16 per 64-elem chunk
            uint32_t af[4][4];
#pragma unroll
            for (int ma = 0; ma < 4; ma++)
                ldm_x4(af[ma], abuf + a_off[ma] + 16u * (uint32_t)((2 * ks + a_hi) ^ a_s[ma]));
            uint32_t bf[2][4];
#pragma unroll
            for (int p = 0; p < 2; p++)
                ldm_x4(bf[p], bbuf + b_off[p] + 16u * (uint32_t)((2 * ks + b_hi) ^ b_s[p]));
#pragma unroll
            for (int ma = 0; ma < 4; ma++) {
#pragma unroll
                for (int na = 0; na < 4; na++) {
                    int p = na >> 1, q = (na & 1) * 2;
                    mma_bf16(acc[ma][na], af[ma], bf[p][q], bf[p][q + 1]);
                }
            }
        }
        buf  = (buf  == 2) ? 0 : buf  + 1;
        nbuf = (nbuf == 2) ? 0 : nbuf + 1;
    }

    // ---- epilogue: scale and store ----
    const int qn = (lane & 3) * 2;
    float2 wsc[4];
#pragma unroll
    for (int na = 0; na < 4; na++)
        wsc[na] = *reinterpret_cast<const float2*>(&wscale[e * NTOT + n0 + wn + na * 8 + qn]);

#pragma unroll
    for (int ma = 0; ma < 4; ma++) {
#pragma unroll
        for (int h = 0; h < 2; h++) {
            int m = m0 + wm + ma * 16 + (lane >> 2) + h * 8;
            if (m >= cnt) continue;
            int entry = base + m;
            float fsc;
            float* orow;
            if (FC1) { fsc = g_xs[g_tok_list[entry]]; orow = g_h + (size_t)entry * N1; }
            else     { fsc = g_as[entry] * g_entry_gate[entry]; orow = g_y + (size_t)entry * H_DIM; }
#pragma unroll
            for (int na = 0; na < 4; na++) {
                float2 o;
                o.x = acc[ma][na][2 * h + 0] * fsc * wsc[na].x;
                o.y = acc[ma][na][2 * h + 1] * fsc * wsc[na].y;
                *reinterpret_cast<float2*>(orow + n0 + wn + na * 8 + qn) = o;
            }
        }
    }
}

// ---------------- SwiGLU + dynamic int8 re-quant (stored as bf16) ----------------
__global__ void __launch_bounds__(256) swiglu_quant_kernel() {
    int entry = blockIdx.x;
    int tid = threadIdx.x, lane = tid & 31, warp = tid >> 5;
    const float* hr = g_h + (size_t)entry * N1;

    __shared__ __align__(16) float a_sh[I_DIM];
    __shared__ float wmax[8];
    __shared__ float sS;

    float pm = 0.0f;
    for (int w4 = tid; w4 < I_DIM / 4; w4 += 256) {   // 352 float4 groups
        float4 h1 = *reinterpret_cast<const float4*>(hr + 4 * w4);
        float4 h2 = *reinterpret_cast<const float4*>(hr + I_DIM + 4 * w4);
        float4 a;
        a.x = h1.x * sigmoid_fast(h1.x) * h2.x;
        a.y = h1.y * sigmoid_fast(h1.y) * h2.y;
        a.z = h1.z * sigmoid_fast(h1.z) * h2.z;
        a.w = h1.w * sigmoid_fast(h1.w) * h2.w;
        *reinterpret_cast<float4*>(&a_sh[4 * w4]) = a;
        pm = fmaxf(pm, fmaxf(fmaxf(fabsf(a.x), fabsf(a.y)),
                             fmaxf(fabsf(a.z), fabsf(a.w))));
    }
    for (int off = 16; off; off >>= 1)
        pm = fmaxf(pm, __shfl_down_sync(0xffffffffu, pm, off));
    if (lane == 0) wmax[warp] = pm;
    __syncthreads();
    if (tid == 0) {
        float mx = 0.0f;
        for (int w = 0; w < 8; w++) mx = fmaxf(mx, wmax[w]);
        float s = fmaxf(mx / 127.0f, 1e-8f);
        g_as[entry] = s; sS = s;
    }
    __syncthreads();
    float s = sS;
    if (tid < I_DIM / 8) {   // 176 groups of 8
        float4 v0 = *reinterpret_cast<const float4*>(&a_sh[8 * tid]);
        float4 v1 = *reinterpret_cast<const float4*>(&a_sh[8 * tid + 4]);
        __align__(16) __nv_bfloat16 q[8] = {
            qb(v0.x, s), qb(v0.y, s), qb(v0.z, s), qb(v0.w, s),
            qb(v1.x, s), qb(v1.y, s), qb(v1.z, s), qb(v1.w, s)};
        *reinterpret_cast<uint4*>(g_ab + (size_t)entry * I_DIM + 8 * tid) =
            *reinterpret_cast<uint4*>(q);
    }
}

// ---------------- combine ----------------
__global__ void __launch_bounds__(256) combine_kernel(const float* __restrict__ shared_out,
                                                      float* __restrict__ out) {
    int t = blockIdx.x;
    int p0 = g_entry_of[2 * t];
    int p1 = g_entry_of[2 * t + 1];
    const float4* s4 = reinterpret_cast<const float4*>(shared_out + (size_t)t * H_DIM);
    const float4* y0 = reinterpret_cast<const float4*>(g_y + (size_t)p0 * H_DIM);
    const float4* y1 = reinterpret_cast<const float4*>(g_y + (size_t)p1 * H_DIM);
    float4* o4 = reinterpret_cast<float4*>(out + (size_t)t * H_DIM);
    for (int w = threadIdx.x; w < H_DIM / 4; w += 256) {
        float4 a = s4[w], b = y0[w], c = y1[w];
        float4 r;
        r.x = a.x + b.x + c.x; r.y = a.y + b.y + c.y;
        r.z = a.z + b.z + c.z; r.w = a.w + b.w + c.w;
        o4[w] = r;
    }
}

// ---------------- launch ----------------
extern "C" void kernel_launch(void* const* d_in, const int* in_sizes, int n_in,
                              void* d_out, int out_size) {
    const float* x    = (const float*)d_in[0];
    const float* gw   = (const float*)d_in[1];
    const int*   w13q = (const int*)  d_in[2];
    const float* w13s = (const float*)d_in[3];
    const int*   w2q  = (const int*)  d_in[4];
    const float* w2s  = (const float*)d_in[5];
    const float* shr  = (const float*)d_in[6];
    float* out = (float*)d_out;

    const int SMEM_SZ = 1024 + 3 * 32768;   // align slack + 3-stage A/B
    static bool attr_set = false;
    if (!attr_set) {
        cudaFuncSetAttribute(gemm_kernel<32, true>,
                             cudaFuncAttributeMaxDynamicSharedMemorySize, SMEM_SZ);
        cudaFuncSetAttribute(gemm_kernel<22, false>,
                             cudaFuncAttributeMaxDynamicSharedMemorySize, SMEM_SZ);
        attr_set = true;
    }

    const int n8_w13 = E_NUM * N1 * H_DIM / 8;     // 5,767,168
    const int n8_w2  = E_NUM * H_DIM * I_DIM / 8;  // 2,883,584
    const int n8_tot = n8_w13 + n8_w2;

    // fork: weight conversion runs concurrently with gating/routing branch
    cudaEventRecord(g_ev0, 0);
    cudaStreamWaitEvent(g_s2, g_ev0, 0);
    convb_all_kernel<<<(n8_tot + 255) / 256, 256, 0, g_s2>>>(w13q, w2q, n8_w13, n8_tot);
    cudaEventRecord(g_ev1, g_s2);

    init_kernel<<<1, 32>>>();
    gate_quant_kernel<<<T_TOKENS, 256>>>(x, gw);
    prefix_kernel<<<1, 32>>>();
    scatter_kernel<<<(T_TOKENS + 255) / 256, 256>>>();

    // join: FC1 needs both converted weights and routed tokens
    cudaStreamWaitEvent(0, g_ev1, 0);

    gemm_kernel<32, true><<<dim3(N1 / 128, T_TOKENS / 128, E_NUM), 256, SMEM_SZ>>>(w13s);
    swiglu_quant_kernel<<<ENTRIES, 256>>>();
    gemm_kernel<22, false><<<dim3(H_DIM / 128, T_TOKENS / 128, E_NUM), 256, SMEM_SZ>>>(w2s);
    combine_kernel<<<T_TOKENS, 256>>>(shr, out);
}